// round 10
// baseline (speedup 1.0000x reference)
#include <cuda_runtime.h>
#include <math.h>

#define B_  2
#define T_  2048
#define C_  1024
#define H_  16
#define HD_ 64
#define N1_ 6
#define N2_ 4

// ---------------- scratch (device globals; no allocs allowed) ----------------
__device__ float g_qkv[B_ * T_ * 3 * C_];          // [B,T,3C]
__device__ float g_q[B_ * H_ * T_ * HD_];          // [B,H,T,64]  (scales folded in)
__device__ float g_k[B_ * H_ * T_ * HD_];
__device__ float g_v[B_ * H_ * T_ * HD_];
__device__ float g_y[B_ * T_ * C_];                // attention out, [B,T,C]
__device__ float g_tq[B_ * N2_ * T_];              // hyperbolic tq
__device__ float g_tk[B_ * N2_ * T_];              // hyperbolic tk

// ---------------- tf32 mma helpers -------------------------------------------
__device__ __forceinline__ unsigned f2tf32(float x) {
    unsigned u;
    asm("cvt.rna.tf32.f32 %0, %1;" : "=r"(u) : "f"(x));
    return u;
}

// D = A(16x8, row) * B(8x8, col) + D, fp32 accum
__device__ __forceinline__ void mma_tf32(float* c, const unsigned* a,
                                         unsigned b0, unsigned b1) {
    asm volatile(
        "mma.sync.aligned.m16n8k8.row.col.f32.tf32.tf32.f32 "
        "{%0,%1,%2,%3}, {%4,%5,%6,%7}, {%8,%9}, {%0,%1,%2,%3};"
        : "+f"(c[0]), "+f"(c[1]), "+f"(c[2]), "+f"(c[3])
        : "r"(a[0]), "r"(a[1]), "r"(a[2]), "r"(a[3]), "r"(b0), "r"(b1));
}

// ---------------- GEMM: C[m,n] = sum_k A[m,k]*B[n,k] (+bias[n]) --------------
// CTA: 256 thr (8 warps), tile 128(M) x 128(N), k-chunk 16, double-buffered.
// Warp tile 32(M) x 64(N).
template <bool BIAS>
__global__ void __launch_bounds__(256) gemm_tf32(const float* __restrict__ A,
                                                 const float* __restrict__ Bm,
                                                 const float* __restrict__ bias,
                                                 float* __restrict__ Cc,
                                                 int M, int N, int K)
{
    __shared__ unsigned As[2][128 * 20];   // tf32 bits, row stride 20 (bank-safe)
    __shared__ unsigned Bs[2][128 * 20];

    const int tid = threadIdx.x;
    const int lane = tid & 31;
    const int wid = tid >> 5;
    const int g = lane >> 2;      // 0..7
    const int c4 = lane & 3;      // 0..3
    const int m0 = blockIdx.y * 128;
    const int n0 = blockIdx.x * 128;
    const int wm = (wid >> 1) * 32;
    const int wn = (wid & 1) * 64;

    float acc[2][8][4];
#pragma unroll
    for (int mt = 0; mt < 2; ++mt)
#pragma unroll
        for (int nt = 0; nt < 8; ++nt)
#pragma unroll
            for (int r = 0; r < 4; ++r) acc[mt][nt][r] = 0.f;

    const int lrow0 = tid >> 2;           // 0..63
    const int lrow1 = lrow0 + 64;         // 64..127
    const int lj = (tid & 3) * 4;

    float4 ra0, ra1, rb0, rb1;

    // initial load (k0 = 0)
    ra0 = *(const float4*)(A + (long)(m0 + lrow0) * K + lj);
    ra1 = *(const float4*)(A + (long)(m0 + lrow1) * K + lj);
    rb0 = *(const float4*)(Bm + (long)(n0 + lrow0) * K + lj);
    rb1 = *(const float4*)(Bm + (long)(n0 + lrow1) * K + lj);
    {
        uint4 u;
        u.x = f2tf32(ra0.x); u.y = f2tf32(ra0.y); u.z = f2tf32(ra0.z); u.w = f2tf32(ra0.w);
        *(uint4*)&As[0][lrow0 * 20 + lj] = u;
        u.x = f2tf32(ra1.x); u.y = f2tf32(ra1.y); u.z = f2tf32(ra1.z); u.w = f2tf32(ra1.w);
        *(uint4*)&As[0][lrow1 * 20 + lj] = u;
        u.x = f2tf32(rb0.x); u.y = f2tf32(rb0.y); u.z = f2tf32(rb0.z); u.w = f2tf32(rb0.w);
        *(uint4*)&Bs[0][lrow0 * 20 + lj] = u;
        u.x = f2tf32(rb1.x); u.y = f2tf32(rb1.y); u.z = f2tf32(rb1.z); u.w = f2tf32(rb1.w);
        *(uint4*)&Bs[0][lrow1 * 20 + lj] = u;
    }
    __syncthreads();

    int stage = 0;
    for (int k0 = 0; k0 < K; k0 += 16) {
        const bool more = (k0 + 16) < K;
        if (more) {
            const int kn = k0 + 16;
            ra0 = *(const float4*)(A + (long)(m0 + lrow0) * K + kn + lj);
            ra1 = *(const float4*)(A + (long)(m0 + lrow1) * K + kn + lj);
            rb0 = *(const float4*)(Bm + (long)(n0 + lrow0) * K + kn + lj);
            rb1 = *(const float4*)(Bm + (long)(n0 + lrow1) * K + kn + lj);
        }

        const unsigned* Asb = As[stage];
        const unsigned* Bsb = Bs[stage];
#pragma unroll
        for (int ks = 0; ks < 2; ++ks) {
            const int kc = 8 * ks + c4;
            unsigned af[2][4], bf[8][2];
#pragma unroll
            for (int mt = 0; mt < 2; ++mt) {
                int r = wm + 16 * mt + g;
                af[mt][0] = Asb[r * 20 + kc];
                af[mt][1] = Asb[(r + 8) * 20 + kc];
                af[mt][2] = Asb[r * 20 + kc + 4];
                af[mt][3] = Asb[(r + 8) * 20 + kc + 4];
            }
#pragma unroll
            for (int nt = 0; nt < 8; ++nt) {
                int n = wn + 8 * nt + g;
                bf[nt][0] = Bsb[n * 20 + kc];
                bf[nt][1] = Bsb[n * 20 + kc + 4];
            }
#pragma unroll
            for (int mt = 0; mt < 2; ++mt)
#pragma unroll
                for (int nt = 0; nt < 8; ++nt)
                    mma_tf32(acc[mt][nt], af[mt], bf[nt][0], bf[nt][1]);
        }

        if (more) {
            unsigned* Asn = As[stage ^ 1];
            unsigned* Bsn = Bs[stage ^ 1];
            uint4 u;
            u.x = f2tf32(ra0.x); u.y = f2tf32(ra0.y); u.z = f2tf32(ra0.z); u.w = f2tf32(ra0.w);
            *(uint4*)&Asn[lrow0 * 20 + lj] = u;
            u.x = f2tf32(ra1.x); u.y = f2tf32(ra1.y); u.z = f2tf32(ra1.z); u.w = f2tf32(ra1.w);
            *(uint4*)&Asn[lrow1 * 20 + lj] = u;
            u.x = f2tf32(rb0.x); u.y = f2tf32(rb0.y); u.z = f2tf32(rb0.z); u.w = f2tf32(rb0.w);
            *(uint4*)&Bsn[lrow0 * 20 + lj] = u;
            u.x = f2tf32(rb1.x); u.y = f2tf32(rb1.y); u.z = f2tf32(rb1.z); u.w = f2tf32(rb1.w);
            *(uint4*)&Bsn[lrow1 * 20 + lj] = u;
            __syncthreads();
        }
        stage ^= 1;
    }

#pragma unroll
    for (int mt = 0; mt < 2; ++mt) {
#pragma unroll
        for (int nt = 0; nt < 8; ++nt) {
            const int rr = m0 + wm + 16 * mt + g;
            const int cc = n0 + wn + 8 * nt + 2 * c4;
            float b0v = 0.f, b1v = 0.f;
            if (BIAS) { b0v = bias[cc]; b1v = bias[cc + 1]; }
            float2 v0; v0.x = acc[mt][nt][0] + b0v; v0.y = acc[mt][nt][1] + b1v;
            float2 v1; v1.x = acc[mt][nt][2] + b0v; v1.y = acc[mt][nt][3] + b1v;
            *(float2*)(Cc + (long)rr * N + cc) = v0;
            *(float2*)(Cc + (long)(rr + 8) * N + cc) = v1;
        }
    }
}

// ---------------- RoPE + per-head prep ---------------------------------------
__global__ void __launch_bounds__(512) rope_kernel(const float* __restrict__ curvp)
{
    const int bt = blockIdx.x;
    const int b = bt / T_;
    const int t = bt % T_;
    const int tid = threadIdx.x;
    const int h = tid >> 5;
    const int j = tid & 31;

    __shared__ float s_inv[32];
    if (tid < 32) s_inv[tid] = (float)pow(10000.0, -(double)tid / 32.0);
    __syncthreads();

    const float* qp = g_qkv + (long)bt * (3 * C_);

    float q1 = qp[h * 64 + j];
    float q2 = qp[h * 64 + 32 + j];
    float k1 = qp[C_ + h * 64 + j];
    float k2 = qp[C_ + h * 64 + 32 + j];

    float fr = (float)t * s_inv[j];
    float cs, sn;
    sincosf(fr, &sn, &cs);

    float q1r = q1 * cs + q2 * sn;
    float q2r = -q1 * sn + q2 * cs;
    float k1r = k1 * cs + k2 * sn;
    float k2r = -k1 * sn + k2 * cs;

    float sq = q1 * q1 + q2 * q2;
    float sk = k1 * k1 + k2 * k2;
#pragma unroll
    for (int o = 16; o > 0; o >>= 1) {
        sq += __shfl_xor_sync(0xffffffffu, sq, o);
        sk += __shfl_xor_sync(0xffffffffu, sk, o);
    }

    float qscale = 1.f, kscale = 1.f;
    if (h < N1_) {
        qscale = 0.125f;
    } else if (h < N1_ + N2_) {
        float curv = curvp[h - N1_];
        if (j == 0) {
            g_tq[(b * N2_ + (h - N1_)) * T_ + t] = sqrtf(1.0f / curv + sq);
            g_tk[(b * N2_ + (h - N1_)) * T_ + t] = sqrtf(1.0f / curv + sk);
        }
    } else {
        qscale = 8.0f / fmaxf(sqrtf(sq), 1e-12f);
        kscale = 1.0f / fmaxf(sqrtf(sk), 1e-12f);
    }

    const long o = ((long)(b * H_ + h) * T_ + t) * HD_;
    g_q[o + j]      = q1r * qscale;
    g_q[o + 32 + j] = q2r * qscale;
    g_k[o + j]      = k1r * kscale;
    g_k[o + 32 + j] = k2r * kscale;

    float2 vv = *(const float2*)(qp + 2 * C_ + 2 * tid);
    *(float2*)(g_v + o + (j * 2)) = vv;
}

// ---------------- attention: FA2-style with tf32 mma --------------------------
// grid (T/128, H, B), 256 threads (8 warps). Warp w: q rows i0+16w..+15 (m16).
__device__ __forceinline__ float hypscore(float p, float tq, float tk,
                                          float curv, float invsqc) {
    float a = fmaxf(curv * (tq * tk - p), 1.0f + 1e-7f);
    return 1.0f / (1e-6f + invsqc * acoshf(a));
}

__global__ void __launch_bounds__(256) attn_mma(const float* __restrict__ curvp)
{
    __shared__ unsigned Ks[64 * 68];   // tf32 bits; stride 68 (≡4 mod 32)
    __shared__ unsigned Vs[64 * 72];   // tf32 bits; stride 72 (≡8 mod 32)
    __shared__ float tks[64];

    const int i0 = blockIdx.x * 128;
    const int h  = blockIdx.y;
    const int b  = blockIdx.z;
    const int tid = threadIdx.x;
    const int w = tid >> 5;
    const int lane = tid & 31;
    const int g = lane >> 2;
    const int c4 = lane & 3;
    const int variant = (h < N1_) ? 0 : ((h < N1_ + N2_) ? 1 : 2);
    const long base = (long)(b * H_ + h) * T_ * HD_;
    const int r0 = 16 * w + g;         // warp-local row 0..127 (and r0+8)

    // ---- stage Q (two 64-row phases through Ks), build register A-fragments --
    unsigned qa[8][4];
#pragma unroll
    for (int ph = 0; ph < 2; ++ph) {
        for (int idx = tid; idx < 64 * 16; idx += 256) {
            int row = idx >> 4, j = (idx & 15) * 4;
            float4 v = *(const float4*)(g_q + base + (long)(i0 + ph * 64 + row) * HD_ + j);
            uint4 u;
            u.x = __float_as_uint(v.x); u.y = __float_as_uint(v.y);
            u.z = __float_as_uint(v.z); u.w = __float_as_uint(v.w);
            *(uint4*)&Ks[row * 68 + j] = u;
        }
        __syncthreads();
        if ((w >> 2) == ph) {
            const int rl = 16 * (w & 3) + g;
#pragma unroll
            for (int kt = 0; kt < 8; ++kt) {
                int col = 8 * kt + c4;
                qa[kt][0] = f2tf32(__uint_as_float(Ks[rl * 68 + col]));
                qa[kt][1] = f2tf32(__uint_as_float(Ks[(rl + 8) * 68 + col]));
                qa[kt][2] = f2tf32(__uint_as_float(Ks[rl * 68 + col + 4]));
                qa[kt][3] = f2tf32(__uint_as_float(Ks[(rl + 8) * 68 + col + 4]));
            }
        }
        __syncthreads();
    }

    float curv = 0.f, invsqc = 0.f, tq0 = 0.f, tq1 = 0.f;
    if (variant == 1) {
        curv = curvp[h - N1_];
        invsqc = sqrtf(1.0f / curv);
        tq0 = g_tq[(b * N2_ + (h - N1_)) * T_ + i0 + r0];
        tq1 = g_tq[(b * N2_ + (h - N1_)) * T_ + i0 + r0 + 8];
    }

    float m0r = -1e30f, m1r = -1e30f, l0 = 0.f, l1 = 0.f;
    float acc[8][4];
#pragma unroll
    for (int nt = 0; nt < 8; ++nt)
#pragma unroll
        for (int r = 0; r < 4; ++r) acc[nt][r] = 0.f;

    const int srcA = (lane & 28) | (c4 >> 1);
    const int srcB = srcA + 2;
    const bool odd = (c4 & 1);
    const int s_last = i0 + ((w >> 2) ? 64 : 0);   // last s-tile this warp computes

    for (int s0 = 0; s0 <= i0 + 64; s0 += 64) {
        // load K/V tiles, converting to tf32 at store time
        for (int idx = tid; idx < 64 * 16; idx += 256) {
            int row = idx >> 4, j = (idx & 15) * 4;
            float4 kv = *(const float4*)(g_k + base + (long)(s0 + row) * HD_ + j);
            uint4 uk;
            uk.x = f2tf32(kv.x); uk.y = f2tf32(kv.y);
            uk.z = f2tf32(kv.z); uk.w = f2tf32(kv.w);
            *(uint4*)&Ks[row * 68 + j] = uk;
            float4 vv = *(const float4*)(g_v + base + (long)(s0 + row) * HD_ + j);
            uint4 uv;
            uv.x = f2tf32(vv.x); uv.y = f2tf32(vv.y);
            uv.z = f2tf32(vv.z); uv.w = f2tf32(vv.w);
            *(uint4*)&Vs[row * 72 + j] = uv;
        }
        if (variant == 1 && tid < 64)
            tks[tid] = g_tk[(b * N2_ + (h - N1_)) * T_ + s0 + tid];
        __syncthreads();

        if (s0 <= s_last) {
            // ---- QK^T: scores 16x64 per warp ----
            float sc[8][4];
#pragma unroll
            for (int nt = 0; nt < 8; ++nt)
#pragma unroll
                for (int r = 0; r < 4; ++r) sc[nt][r] = 0.f;

#pragma unroll
            for (int nt = 0; nt < 8; ++nt) {
#pragma unroll
                for (int kt = 0; kt < 8; ++kt) {
                    unsigned b0 = Ks[(8 * nt + g) * 68 + 8 * kt + c4];
                    unsigned b1 = Ks[(8 * nt + g) * 68 + 8 * kt + c4 + 4];
                    mma_tf32(sc[nt], qa[kt], b0, b1);
                }
            }

            // ---- transform + mask + row max ----
            const bool domask = (s0 + 63 > i0 + 16 * w);
            const int gr0 = i0 + r0;
            float mloc0 = -1e30f, mloc1 = -1e30f;
#pragma unroll
            for (int nt = 0; nt < 8; ++nt) {
                const int gc = s0 + 8 * nt + 2 * c4;
                if (variant == 1) {
                    float tk0 = tks[8 * nt + 2 * c4], tk1 = tks[8 * nt + 2 * c4 + 1];
                    sc[nt][0] = hypscore(sc[nt][0], tq0, tk0, curv, invsqc);
                    sc[nt][1] = hypscore(sc[nt][1], tq0, tk1, curv, invsqc);
                    sc[nt][2] = hypscore(sc[nt][2], tq1, tk0, curv, invsqc);
                    sc[nt][3] = hypscore(sc[nt][3], tq1, tk1, curv, invsqc);
                }
                if (domask) {
                    if (gc > gr0)         sc[nt][0] = -1e30f;
                    if (gc + 1 > gr0)     sc[nt][1] = -1e30f;
                    if (gc > gr0 + 8)     sc[nt][2] = -1e30f;
                    if (gc + 1 > gr0 + 8) sc[nt][3] = -1e30f;
                }
                mloc0 = fmaxf(mloc0, fmaxf(sc[nt][0], sc[nt][1]));
                mloc1 = fmaxf(mloc1, fmaxf(sc[nt][2], sc[nt][3]));
            }
            mloc0 = fmaxf(mloc0, __shfl_xor_sync(0xffffffffu, mloc0, 1));
            mloc0 = fmaxf(mloc0, __shfl_xor_sync(0xffffffffu, mloc0, 2));
            mloc1 = fmaxf(mloc1, __shfl_xor_sync(0xffffffffu, mloc1, 1));
            mloc1 = fmaxf(mloc1, __shfl_xor_sync(0xffffffffu, mloc1, 2));

            const float mn0 = fmaxf(m0r, mloc0);
            const float mn1 = fmaxf(m1r, mloc1);
            const float f0 = __expf(m0r - mn0);
            const float f1 = __expf(m1r - mn1);
            l0 *= f0; l1 *= f1;
#pragma unroll
            for (int nt = 0; nt < 8; ++nt) {
                acc[nt][0] *= f0; acc[nt][1] *= f0;
                acc[nt][2] *= f1; acc[nt][3] *= f1;
            }

            float s0sum = 0.f, s1sum = 0.f;
#pragma unroll
            for (int nt = 0; nt < 8; ++nt) {
                sc[nt][0] = __expf(sc[nt][0] - mn0);
                sc[nt][1] = __expf(sc[nt][1] - mn0);
                sc[nt][2] = __expf(sc[nt][2] - mn1);
                sc[nt][3] = __expf(sc[nt][3] - mn1);
                s0sum += sc[nt][0] + sc[nt][1];
                s1sum += sc[nt][2] + sc[nt][3];
            }
            s0sum += __shfl_xor_sync(0xffffffffu, s0sum, 1);
            s0sum += __shfl_xor_sync(0xffffffffu, s0sum, 2);
            s1sum += __shfl_xor_sync(0xffffffffu, s1sum, 1);
            s1sum += __shfl_xor_sync(0xffffffffu, s1sum, 2);
            l0 += s0sum; l1 += s1sum;
            m0r = mn0; m1r = mn1;

            // ---- P·V: re-layout P (C-frag -> A-frag) via shfl, then mma ----
#pragma unroll
            for (int kt = 0; kt < 8; ++kt) {
                float x0 = __shfl_sync(0xffffffffu, sc[kt][0], srcA);
                float x1 = __shfl_sync(0xffffffffu, sc[kt][1], srcA);
                float y0 = __shfl_sync(0xffffffffu, sc[kt][0], srcB);
                float y1 = __shfl_sync(0xffffffffu, sc[kt][1], srcB);
                float z0 = __shfl_sync(0xffffffffu, sc[kt][2], srcA);
                float z1 = __shfl_sync(0xffffffffu, sc[kt][3], srcA);
                float u0 = __shfl_sync(0xffffffffu, sc[kt][2], srcB);
                float u1 = __shfl_sync(0xffffffffu, sc[kt][3], srcB);
                unsigned pa[4];
                pa[0] = f2tf32(odd ? x1 : x0);
                pa[1] = f2tf32(odd ? z1 : z0);
                pa[2] = f2tf32(odd ? y1 : y0);
                pa[3] = f2tf32(odd ? u1 : u0);
#pragma unroll
                for (int nt = 0; nt < 8; ++nt) {
                    unsigned b0 = Vs[(8 * kt + c4) * 72 + 8 * nt + g];
                    unsigned b1 = Vs[(8 * kt + c4 + 4) * 72 + 8 * nt + g];
                    mma_tf32(acc[nt], pa, b0, b1);
                }
            }
        }
        __syncthreads();
    }

    // ---- epilogue ----
    const float il0 = 1.0f / l0;
    const float il1 = 1.0f / l1;
    const int r = i0 + r0;
    float* y0p = g_y + (long)(b * T_ + r) * C_ + h * HD_;
    float* y1p = g_y + (long)(b * T_ + r + 8) * C_ + h * HD_;
#pragma unroll
    for (int nt = 0; nt < 8; ++nt) {
        float2 o0; o0.x = acc[nt][0] * il0; o0.y = acc[nt][1] * il0;
        float2 o1; o1.x = acc[nt][2] * il1; o1.y = acc[nt][3] * il1;
        *(float2*)(y0p + 8 * nt + 2 * c4) = o0;
        *(float2*)(y1p + 8 * nt + 2 * c4) = o1;
    }
}

// ---------------- launch ------------------------------------------------------
extern "C" void kernel_launch(void* const* d_in, const int* in_sizes, int n_in,
                              void* d_out, int out_size)
{
    const float* x       = (const float*)d_in[0];
    const float* qkv_w   = (const float*)d_in[1];
    const float* proj_w  = (const float*)d_in[2];
    const float* proj_b  = (const float*)d_in[3];
    const float* curv    = (const float*)d_in[4];
    float* out = (float*)d_out;

    float *qkv, *y;
    cudaGetSymbolAddress((void**)&qkv, g_qkv);
    cudaGetSymbolAddress((void**)&y,   g_y);

    // 1) qkv = x @ qkv_w.T   [4096, 3072]
    gemm_tf32<false><<<dim3((3 * C_) / 128, (B_ * T_) / 128), 256>>>(
        x, qkv_w, nullptr, qkv, B_ * T_, 3 * C_, C_);

    // 2) rope + head layout + scale folding + hyperbolic tq/tk
    rope_kernel<<<B_ * T_, 512>>>(curv);

    // 3) multi-geometry causal attention (tf32 tensor cores) -> g_y [B,T,C]
    attn_mma<<<dim3(T_ / 128, H_, B_), 256>>>(curv);

    // 4) out = y @ proj_w.T + proj_b
    gemm_tf32<true><<<dim3(C_ / 128, (B_ * T_) / 128), 256>>>(
        y, proj_w, proj_b, out, B_ * T_, C_, C_);
}

// round 13
// speedup vs baseline: 1.1678x; 1.1678x over previous
#include <cuda_runtime.h>
#include <stdint.h>
#include <math.h>

#define B_  2
#define T_  2048
#define C_  1024
#define H_  16
#define HD_ 64
#define N1_ 6
#define N2_ 4

// ---------------- scratch (device globals; no allocs allowed) ----------------
__device__ float g_qkv[B_ * T_ * 3 * C_];          // [B,T,3C] fp32
__device__ float g_q[B_ * H_ * T_ * HD_];          // [B,H,T,64] tf32-rounded
__device__ float g_k[B_ * H_ * T_ * HD_];          // tf32-rounded
__device__ float g_v[B_ * H_ * T_ * HD_];          // tf32-rounded
__device__ float g_y[B_ * T_ * C_];                // attn out, tf32-rounded
__device__ float g_tq[B_ * N2_ * T_];
__device__ float g_tk[B_ * N2_ * T_];
__device__ float g_xa[B_ * T_ * C_];               // x, tf32-rounded
__device__ float g_wa[3 * C_ * C_];                // qkv_w, tf32-rounded
__device__ float g_pw[C_ * C_];                    // proj_w, tf32-rounded

// ---------------- helpers -----------------------------------------------------
__device__ __forceinline__ unsigned f2tf32(float x) {
    unsigned u;
    asm("cvt.rna.tf32.f32 %0, %1;" : "=r"(u) : "f"(x));
    return u;
}
__device__ __forceinline__ unsigned sptr(const void* p) {
    return (unsigned)__cvta_generic_to_shared(p);
}
__device__ __forceinline__ void cp16(unsigned s, const void* g) {
    asm volatile("cp.async.cg.shared.global [%0], [%1], 16;" :: "r"(s), "l"(g));
}
__device__ __forceinline__ void cp_commit() {
    asm volatile("cp.async.commit_group;");
}
__device__ __forceinline__ void cp_wait0() {
    asm volatile("cp.async.wait_group 0;");
}

// D = A(16x8, row) * B(8x8, col) + D, fp32 accum
__device__ __forceinline__ void mma_tf32(float* c, const unsigned* a,
                                         unsigned b0, unsigned b1) {
    asm volatile(
        "mma.sync.aligned.m16n8k8.row.col.f32.tf32.tf32.f32 "
        "{%0,%1,%2,%3}, {%4,%5,%6,%7}, {%8,%9}, {%0,%1,%2,%3};"
        : "+f"(c[0]), "+f"(c[1]), "+f"(c[2]), "+f"(c[3])
        : "r"(a[0]), "r"(a[1]), "r"(a[2]), "r"(a[3]), "r"(b0), "r"(b1));
}

// ---------------- tf32 pre-convert -------------------------------------------
__global__ void prep_tf32(const float* __restrict__ in, float* __restrict__ out,
                          int n4)
{
    int i = blockIdx.x * blockDim.x + threadIdx.x;
    if (i < n4) {
        float4 v = ((const float4*)in)[i];
        uint4 u;
        u.x = f2tf32(v.x); u.y = f2tf32(v.y); u.z = f2tf32(v.z); u.w = f2tf32(v.w);
        ((uint4*)out)[i] = u;
    }
}

// ---------------- GEMM: C[m,n] = sum_k A[m,k]*B[n,k] (+bias[n]) --------------
// Inputs already tf32-rounded. CTA 256 thr, tile 128x128, k-chunk 16,
// cp.async double-buffered. Warp tile 32x64.
template <bool BIAS>
__global__ void __launch_bounds__(256, 2) gemm_tf32(const float* __restrict__ A,
                                                    const float* __restrict__ Bm,
                                                    const float* __restrict__ bias,
                                                    float* __restrict__ Cc,
                                                    int M, int N, int K)
{
    __shared__ unsigned As[2][128 * 20];
    __shared__ unsigned Bs[2][128 * 20];

    const int tid = threadIdx.x;
    const int lane = tid & 31;
    const int wid = tid >> 5;
    const int g = lane >> 2;
    const int c4 = lane & 3;
    const int m0 = blockIdx.y * 128;
    const int n0 = blockIdx.x * 128;
    const int wm = (wid >> 1) * 32;
    const int wn = (wid & 1) * 64;

    const int lrow0 = tid >> 2;           // 0..63, 4 threads/row
    const int lrow1 = lrow0 + 64;
    const int lj = (tid & 3) * 4;         // 0,4,8,12 -> full 16-float k-row

    float acc[2][8][4];
#pragma unroll
    for (int mt = 0; mt < 2; ++mt)
#pragma unroll
        for (int nt = 0; nt < 8; ++nt)
#pragma unroll
            for (int r = 0; r < 4; ++r) acc[mt][nt][r] = 0.f;

    // prologue: tile k0=0 into buffer 0
    cp16(sptr(&As[0][lrow0 * 20 + lj]), A + (long)(m0 + lrow0) * K + lj);
    cp16(sptr(&As[0][lrow1 * 20 + lj]), A + (long)(m0 + lrow1) * K + lj);
    cp16(sptr(&Bs[0][lrow0 * 20 + lj]), Bm + (long)(n0 + lrow0) * K + lj);
    cp16(sptr(&Bs[0][lrow1 * 20 + lj]), Bm + (long)(n0 + lrow1) * K + lj);
    cp_commit();

    int buf = 0;
    for (int k0 = 0; k0 < K; k0 += 16) {
        cp_wait0();
        __syncthreads();
        if (k0 + 16 < K) {
            const int kn = k0 + 16;
            unsigned* Asn = As[buf ^ 1];
            unsigned* Bsn = Bs[buf ^ 1];
            cp16(sptr(&Asn[lrow0 * 20 + lj]), A + (long)(m0 + lrow0) * K + kn + lj);
            cp16(sptr(&Asn[lrow1 * 20 + lj]), A + (long)(m0 + lrow1) * K + kn + lj);
            cp16(sptr(&Bsn[lrow0 * 20 + lj]), Bm + (long)(n0 + lrow0) * K + kn + lj);
            cp16(sptr(&Bsn[lrow1 * 20 + lj]), Bm + (long)(n0 + lrow1) * K + kn + lj);
            cp_commit();
        }

        const unsigned* Asb = As[buf];
        const unsigned* Bsb = Bs[buf];
#pragma unroll
        for (int ks = 0; ks < 2; ++ks) {
            const int kc = 8 * ks + c4;
            unsigned af[2][4], bf[8][2];
#pragma unroll
            for (int mt = 0; mt < 2; ++mt) {
                int r = wm + 16 * mt + g;
                af[mt][0] = Asb[r * 20 + kc];
                af[mt][1] = Asb[(r + 8) * 20 + kc];
                af[mt][2] = Asb[r * 20 + kc + 4];
                af[mt][3] = Asb[(r + 8) * 20 + kc + 4];
            }
#pragma unroll
            for (int nt = 0; nt < 8; ++nt) {
                int n = wn + 8 * nt + g;
                bf[nt][0] = Bsb[n * 20 + kc];
                bf[nt][1] = Bsb[n * 20 + kc + 4];
            }
#pragma unroll
            for (int mt = 0; mt < 2; ++mt)
#pragma unroll
                for (int nt = 0; nt < 8; ++nt)
                    mma_tf32(acc[mt][nt], af[mt], bf[nt][0], bf[nt][1]);
        }
        buf ^= 1;
    }

#pragma unroll
    for (int mt = 0; mt < 2; ++mt) {
#pragma unroll
        for (int nt = 0; nt < 8; ++nt) {
            const int rr = m0 + wm + 16 * mt + g;
            const int cc = n0 + wn + 8 * nt + 2 * c4;
            float b0v = 0.f, b1v = 0.f;
            if (BIAS) { b0v = bias[cc]; b1v = bias[cc + 1]; }
            float2 v0; v0.x = acc[mt][nt][0] + b0v; v0.y = acc[mt][nt][1] + b1v;
            float2 v1; v1.x = acc[mt][nt][2] + b0v; v1.y = acc[mt][nt][3] + b1v;
            *(float2*)(Cc + (long)rr * N + cc) = v0;
            *(float2*)(Cc + (long)(rr + 8) * N + cc) = v1;
        }
    }
}

// ---------------- RoPE + per-head prep (writes tf32-rounded q/k/v) ------------
__global__ void __launch_bounds__(512) rope_kernel(const float* __restrict__ curvp)
{
    const int bt = blockIdx.x;
    const int b = bt / T_;
    const int t = bt % T_;
    const int tid = threadIdx.x;
    const int h = tid >> 5;
    const int j = tid & 31;

    __shared__ float s_inv[32];
    if (tid < 32) s_inv[tid] = (float)pow(10000.0, -(double)tid / 32.0);
    __syncthreads();

    const float* qp = g_qkv + (long)bt * (3 * C_);

    float q1 = qp[h * 64 + j];
    float q2 = qp[h * 64 + 32 + j];
    float k1 = qp[C_ + h * 64 + j];
    float k2 = qp[C_ + h * 64 + 32 + j];

    float fr = (float)t * s_inv[j];
    float cs, sn;
    sincosf(fr, &sn, &cs);

    float q1r = q1 * cs + q2 * sn;
    float q2r = -q1 * sn + q2 * cs;
    float k1r = k1 * cs + k2 * sn;
    float k2r = -k1 * sn + k2 * cs;

    float sq = q1 * q1 + q2 * q2;
    float sk = k1 * k1 + k2 * k2;
#pragma unroll
    for (int o = 16; o > 0; o >>= 1) {
        sq += __shfl_xor_sync(0xffffffffu, sq, o);
        sk += __shfl_xor_sync(0xffffffffu, sk, o);
    }

    float qscale = 1.f, kscale = 1.f;
    if (h < N1_) {
        qscale = 0.125f;
    } else if (h < N1_ + N2_) {
        float curv = curvp[h - N1_];
        if (j == 0) {
            g_tq[(b * N2_ + (h - N1_)) * T_ + t] = sqrtf(1.0f / curv + sq);
            g_tk[(b * N2_ + (h - N1_)) * T_ + t] = sqrtf(1.0f / curv + sk);
        }
    } else {
        qscale = 8.0f / fmaxf(sqrtf(sq), 1e-12f);
        kscale = 1.0f / fmaxf(sqrtf(sk), 1e-12f);
    }

    const long o = ((long)(b * H_ + h) * T_ + t) * HD_;
    g_q[o + j]      = __uint_as_float(f2tf32(q1r * qscale));
    g_q[o + 32 + j] = __uint_as_float(f2tf32(q2r * qscale));
    g_k[o + j]      = __uint_as_float(f2tf32(k1r * kscale));
    g_k[o + 32 + j] = __uint_as_float(f2tf32(k2r * kscale));

    float2 vv = *(const float2*)(qp + 2 * C_ + 2 * tid);
    vv.x = __uint_as_float(f2tf32(vv.x));
    vv.y = __uint_as_float(f2tf32(vv.y));
    *(float2*)(g_v + o + (j * 2)) = vv;
}

// ---------------- attention: FA2-style, tf32 mma, cp.async double-buffer ------
__device__ __forceinline__ float hypscore(float p, float tq, float tk,
                                          float curv, float invsqc) {
    float a = fmaxf(curv * (tq * tk - p), 1.0f + 1e-7f);
    return 1.0f / (1e-6f + invsqc * acoshf(a));
}

__global__ void __launch_bounds__(256) attn_mma(const float* __restrict__ curvp)
{
    __shared__ unsigned Ks[2][64 * 68];   // stride 68 (≡4 mod 32)
    __shared__ unsigned Vs[2][64 * 72];   // stride 72 (≡8 mod 32)
    __shared__ float tks[2][64];

    const int i0 = blockIdx.x * 128;
    const int h  = blockIdx.y;
    const int b  = blockIdx.z;
    const int tid = threadIdx.x;
    const int w = tid >> 5;
    const int lane = tid & 31;
    const int g = lane >> 2;
    const int c4 = lane & 3;
    const int variant = (h < N1_) ? 0 : ((h < N1_ + N2_) ? 1 : 2);
    const long base = (long)(b * H_ + h) * T_ * HD_;
    const int r0 = 16 * w + g;

    // ---- stage Q (two 64-row phases through Ks[0]), build A-fragments --------
    unsigned qa[8][4];
#pragma unroll
    for (int ph = 0; ph < 2; ++ph) {
        for (int idx = tid; idx < 64 * 16; idx += 256) {
            int row = idx >> 4, j = (idx & 15) * 4;
            *(uint4*)&Ks[0][row * 68 + j] =
                *(const uint4*)(g_q + base + (long)(i0 + ph * 64 + row) * HD_ + j);
        }
        __syncthreads();
        if ((w >> 2) == ph) {
            const int rl = 16 * (w & 3) + g;
#pragma unroll
            for (int kt = 0; kt < 8; ++kt) {
                int col = 8 * kt + c4;
                qa[kt][0] = Ks[0][rl * 68 + col];
                qa[kt][1] = Ks[0][(rl + 8) * 68 + col];
                qa[kt][2] = Ks[0][rl * 68 + col + 4];
                qa[kt][3] = Ks[0][(rl + 8) * 68 + col + 4];
            }
        }
        __syncthreads();
    }

    float curv = 0.f, invsqc = 0.f, tq0 = 0.f, tq1 = 0.f;
    const float* tkbase = nullptr;
    if (variant == 1) {
        curv = curvp[h - N1_];
        invsqc = sqrtf(1.0f / curv);
        tq0 = g_tq[(b * N2_ + (h - N1_)) * T_ + i0 + r0];
        tq1 = g_tq[(b * N2_ + (h - N1_)) * T_ + i0 + r0 + 8];
        tkbase = g_tk + (b * N2_ + (h - N1_)) * T_;
    }

    float m0r = -1e30f, m1r = -1e30f, l0 = 0.f, l1 = 0.f;
    float acc[8][4];
#pragma unroll
    for (int nt = 0; nt < 8; ++nt)
#pragma unroll
        for (int r = 0; r < 4; ++r) acc[nt][r] = 0.f;

    const int srcA = (lane & 28) | (c4 >> 1);
    const int srcB = srcA + 2;
    const bool odd = (c4 & 1);
    const int s_last = i0 + ((w >> 2) ? 64 : 0);
    const int s_end = i0 + 64;

    const int crow = tid >> 2;            // 0..63 (copy row; 4 threads/row)
    const int cj = (tid & 3) * 4;         // 0,4,8,12

    // prologue: tile s0=0 into buffer 0.
    // NOTE: each row is 64 floats -> each of the 4 threads/row issues 4 cp16s.
    {
        const float* kg = g_k + base + (long)crow * HD_;
        const float* vg = g_v + base + (long)crow * HD_;
#pragma unroll
        for (int c = 0; c < 4; ++c) {
            cp16(sptr(&Ks[0][crow * 68 + cj + 16 * c]), kg + cj + 16 * c);
            cp16(sptr(&Vs[0][crow * 72 + cj + 16 * c]), vg + cj + 16 * c);
        }
        if (variant == 1 && tid < 16)
            cp16(sptr(&tks[0][tid * 4]), tkbase + tid * 4);
        cp_commit();
    }

    int buf = 0;
    for (int s0 = 0; s0 <= s_end; s0 += 64) {
        cp_wait0();
        __syncthreads();
        if (s0 + 64 <= s_end) {
            const float* kg = g_k + base + (long)(s0 + 64 + crow) * HD_;
            const float* vg = g_v + base + (long)(s0 + 64 + crow) * HD_;
#pragma unroll
            for (int c = 0; c < 4; ++c) {
                cp16(sptr(&Ks[buf ^ 1][crow * 68 + cj + 16 * c]), kg + cj + 16 * c);
                cp16(sptr(&Vs[buf ^ 1][crow * 72 + cj + 16 * c]), vg + cj + 16 * c);
            }
            if (variant == 1 && tid < 16)
                cp16(sptr(&tks[buf ^ 1][tid * 4]), tkbase + s0 + 64 + tid * 4);
            cp_commit();
        }

        if (s0 <= s_last) {
            const unsigned* Kb = Ks[buf];
            const unsigned* Vb = Vs[buf];
            const float* tkb = tks[buf];

            // ---- QK^T ----
            float sc[8][4];
#pragma unroll
            for (int nt = 0; nt < 8; ++nt)
#pragma unroll
                for (int r = 0; r < 4; ++r) sc[nt][r] = 0.f;

#pragma unroll
            for (int nt = 0; nt < 8; ++nt) {
#pragma unroll
                for (int kt = 0; kt < 8; ++kt) {
                    unsigned b0 = Kb[(8 * nt + g) * 68 + 8 * kt + c4];
                    unsigned b1 = Kb[(8 * nt + g) * 68 + 8 * kt + c4 + 4];
                    mma_tf32(sc[nt], qa[kt], b0, b1);
                }
            }

            // ---- transform + mask + row max ----
            const bool domask = (s0 + 63 > i0 + 16 * w);
            const int gr0 = i0 + r0;
            float mloc0 = -1e30f, mloc1 = -1e30f;
#pragma unroll
            for (int nt = 0; nt < 8; ++nt) {
                const int gc = s0 + 8 * nt + 2 * c4;
                if (variant == 1) {
                    float tk0 = tkb[8 * nt + 2 * c4], tk1 = tkb[8 * nt + 2 * c4 + 1];
                    sc[nt][0] = hypscore(sc[nt][0], tq0, tk0, curv, invsqc);
                    sc[nt][1] = hypscore(sc[nt][1], tq0, tk1, curv, invsqc);
                    sc[nt][2] = hypscore(sc[nt][2], tq1, tk0, curv, invsqc);
                    sc[nt][3] = hypscore(sc[nt][3], tq1, tk1, curv, invsqc);
                }
                if (domask) {
                    if (gc > gr0)         sc[nt][0] = -1e30f;
                    if (gc + 1 > gr0)     sc[nt][1] = -1e30f;
                    if (gc > gr0 + 8)     sc[nt][2] = -1e30f;
                    if (gc + 1 > gr0 + 8) sc[nt][3] = -1e30f;
                }
                mloc0 = fmaxf(mloc0, fmaxf(sc[nt][0], sc[nt][1]));
                mloc1 = fmaxf(mloc1, fmaxf(sc[nt][2], sc[nt][3]));
            }
            mloc0 = fmaxf(mloc0, __shfl_xor_sync(0xffffffffu, mloc0, 1));
            mloc0 = fmaxf(mloc0, __shfl_xor_sync(0xffffffffu, mloc0, 2));
            mloc1 = fmaxf(mloc1, __shfl_xor_sync(0xffffffffu, mloc1, 1));
            mloc1 = fmaxf(mloc1, __shfl_xor_sync(0xffffffffu, mloc1, 2));

            const float mn0 = fmaxf(m0r, mloc0);
            const float mn1 = fmaxf(m1r, mloc1);
            const float f0 = __expf(m0r - mn0);
            const float f1 = __expf(m1r - mn1);
            l0 *= f0; l1 *= f1;
#pragma unroll
            for (int nt = 0; nt < 8; ++nt) {
                acc[nt][0] *= f0; acc[nt][1] *= f0;
                acc[nt][2] *= f1; acc[nt][3] *= f1;
            }

            float s0sum = 0.f, s1sum = 0.f;
#pragma unroll
            for (int nt = 0; nt < 8; ++nt) {
                sc[nt][0] = __expf(sc[nt][0] - mn0);
                sc[nt][1] = __expf(sc[nt][1] - mn0);
                sc[nt][2] = __expf(sc[nt][2] - mn1);
                sc[nt][3] = __expf(sc[nt][3] - mn1);
                s0sum += sc[nt][0] + sc[nt][1];
                s1sum += sc[nt][2] + sc[nt][3];
            }
            s0sum += __shfl_xor_sync(0xffffffffu, s0sum, 1);
            s0sum += __shfl_xor_sync(0xffffffffu, s0sum, 2);
            s1sum += __shfl_xor_sync(0xffffffffu, s1sum, 1);
            s1sum += __shfl_xor_sync(0xffffffffu, s1sum, 2);
            l0 += s0sum; l1 += s1sum;
            m0r = mn0; m1r = mn1;

            // ---- P·V ----
#pragma unroll
            for (int kt = 0; kt < 8; ++kt) {
                float x0 = __shfl_sync(0xffffffffu, sc[kt][0], srcA);
                float x1 = __shfl_sync(0xffffffffu, sc[kt][1], srcA);
                float y0 = __shfl_sync(0xffffffffu, sc[kt][0], srcB);
                float y1 = __shfl_sync(0xffffffffu, sc[kt][1], srcB);
                float z0 = __shfl_sync(0xffffffffu, sc[kt][2], srcA);
                float z1 = __shfl_sync(0xffffffffu, sc[kt][3], srcA);
                float u0 = __shfl_sync(0xffffffffu, sc[kt][2], srcB);
                float u1 = __shfl_sync(0xffffffffu, sc[kt][3], srcB);
                unsigned pa[4];
                pa[0] = f2tf32(odd ? x1 : x0);
                pa[1] = f2tf32(odd ? z1 : z0);
                pa[2] = f2tf32(odd ? y1 : y0);
                pa[3] = f2tf32(odd ? u1 : u0);
#pragma unroll
                for (int nt = 0; nt < 8; ++nt) {
                    unsigned b0 = Vb[(8 * kt + c4) * 72 + 8 * nt + g];
                    unsigned b1 = Vb[(8 * kt + c4 + 4) * 72 + 8 * nt + g];
                    mma_tf32(acc[nt], pa, b0, b1);
                }
            }
        }
        buf ^= 1;
    }

    // ---- epilogue (write tf32-rounded so proj GEMM can skip conversion) ----
    const float il0 = 1.0f / l0;
    const float il1 = 1.0f / l1;
    const int r = i0 + r0;
    float* y0p = g_y + (long)(b * T_ + r) * C_ + h * HD_;
    float* y1p = g_y + (long)(b * T_ + r + 8) * C_ + h * HD_;
#pragma unroll
    for (int nt = 0; nt < 8; ++nt) {
        float2 o0, o1;
        o0.x = __uint_as_float(f2tf32(acc[nt][0] * il0));
        o0.y = __uint_as_float(f2tf32(acc[nt][1] * il0));
        o1.x = __uint_as_float(f2tf32(acc[nt][2] * il1));
        o1.y = __uint_as_float(f2tf32(acc[nt][3] * il1));
        *(float2*)(y0p + 8 * nt + 2 * c4) = o0;
        *(float2*)(y1p + 8 * nt + 2 * c4) = o1;
    }
}

// ---------------- launch ------------------------------------------------------
extern "C" void kernel_launch(void* const* d_in, const int* in_sizes, int n_in,
                              void* d_out, int out_size)
{
    const float* x       = (const float*)d_in[0];
    const float* qkv_w   = (const float*)d_in[1];
    const float* proj_w  = (const float*)d_in[2];
    const float* proj_b  = (const float*)d_in[3];
    const float* curv    = (const float*)d_in[4];
    float* out = (float*)d_out;

    float *qkv, *y, *xa, *wa, *pw;
    cudaGetSymbolAddress((void**)&qkv, g_qkv);
    cudaGetSymbolAddress((void**)&y,   g_y);
    cudaGetSymbolAddress((void**)&xa,  g_xa);
    cudaGetSymbolAddress((void**)&wa,  g_wa);
    cudaGetSymbolAddress((void**)&pw,  g_pw);

    // 0) tf32 pre-conversion of GEMM inputs
    prep_tf32<<<(B_ * T_ * C_ / 4 + 255) / 256, 256>>>(x, xa, B_ * T_ * C_ / 4);
    prep_tf32<<<(3 * C_ * C_ / 4 + 255) / 256, 256>>>(qkv_w, wa, 3 * C_ * C_ / 4);
    prep_tf32<<<(C_ * C_ / 4 + 255) / 256, 256>>>(proj_w, pw, C_ * C_ / 4);

    // 1) qkv = x @ qkv_w.T   [4096, 3072]
    gemm_tf32<false><<<dim3((3 * C_) / 128, (B_ * T_) / 128), 256>>>(
        xa, wa, nullptr, qkv, B_ * T_, 3 * C_, C_);

    // 2) rope + head layout + scale folding + hyperbolic tq/tk
    rope_kernel<<<B_ * T_, 512>>>(curv);

    // 3) multi-geometry causal attention (tf32 tensor cores) -> g_y [B,T,C]
    attn_mma<<<dim3(T_ / 128, H_, B_), 256>>>(curv);

    // 4) out = y @ proj_w.T + proj_b
    gemm_tf32<true><<<dim3(C_ / 128, (B_ * T_) / 128), 256>>>(
        y, pw, proj_b, out, B_ * T_, C_, C_);
}

// round 14
// speedup vs baseline: 1.1723x; 1.0038x over previous
#include <cuda_runtime.h>
#include <stdint.h>
#include <math.h>

#define B_  2
#define T_  2048
#define C_  1024
#define H_  16
#define HD_ 64
#define N1_ 6
#define N2_ 4

// ---------------- scratch (device globals; no allocs allowed) ----------------
__device__ float g_qkv[B_ * T_ * 3 * C_];          // [B,T,3C] fp32
__device__ float g_q[B_ * H_ * T_ * HD_];          // [B,H,T,64] tf32-rounded
__device__ float g_k[B_ * H_ * T_ * HD_];          // tf32-rounded
__device__ float g_v[B_ * H_ * T_ * HD_];          // tf32-rounded
__device__ float g_y[B_ * T_ * C_];                // attn out, tf32-rounded
__device__ float g_tq[B_ * N2_ * T_];
__device__ float g_tk[B_ * N2_ * T_];
__device__ float g_xa[B_ * T_ * C_];               // x, tf32-rounded
__device__ float g_wa[3 * C_ * C_];                // qkv_w, tf32-rounded
__device__ float g_pw[C_ * C_];                    // proj_w, tf32-rounded

// ---------------- helpers -----------------------------------------------------
__device__ __forceinline__ unsigned f2tf32(float x) {
    unsigned u;
    asm("cvt.rna.tf32.f32 %0, %1;" : "=r"(u) : "f"(x));
    return u;
}
__device__ __forceinline__ unsigned sptr(const void* p) {
    return (unsigned)__cvta_generic_to_shared(p);
}
__device__ __forceinline__ void cp16(unsigned s, const void* g) {
    asm volatile("cp.async.cg.shared.global [%0], [%1], 16;" :: "r"(s), "l"(g));
}
__device__ __forceinline__ void cp_commit() {
    asm volatile("cp.async.commit_group;");
}
__device__ __forceinline__ void cp_wait0() {
    asm volatile("cp.async.wait_group 0;");
}
__device__ __forceinline__ void cp_wait1() {
    asm volatile("cp.async.wait_group 1;");
}

// D = A(16x8, row) * B(8x8, col) + D, fp32 accum
__device__ __forceinline__ void mma_tf32(float* c, const unsigned* a,
                                         unsigned b0, unsigned b1) {
    asm volatile(
        "mma.sync.aligned.m16n8k8.row.col.f32.tf32.tf32.f32 "
        "{%0,%1,%2,%3}, {%4,%5,%6,%7}, {%8,%9}, {%0,%1,%2,%3};"
        : "+f"(c[0]), "+f"(c[1]), "+f"(c[2]), "+f"(c[3])
        : "r"(a[0]), "r"(a[1]), "r"(a[2]), "r"(a[3]), "r"(b0), "r"(b1));
}

// ---------------- tf32 pre-convert -------------------------------------------
__global__ void prep_tf32(const float* __restrict__ in, float* __restrict__ out,
                          int n4)
{
    int i = blockIdx.x * blockDim.x + threadIdx.x;
    if (i < n4) {
        float4 v = ((const float4*)in)[i];
        uint4 u;
        u.x = f2tf32(v.x); u.y = f2tf32(v.y); u.z = f2tf32(v.z); u.w = f2tf32(v.w);
        ((uint4*)out)[i] = u;
    }
}

// ---------------- GEMM: C[m,n] = sum_k A[m,k]*B[n,k] (+bias[n]) --------------
// Inputs already tf32-rounded. CTA 256 thr, tile 128x128, k-chunk 16,
// 3-stage cp.async pipeline. Warp tile 32x64.
#define GSTRIDE 2560   // 128 rows * 20 stride (unsigned units) per stage

template <bool BIAS>
__global__ void __launch_bounds__(256, 2) gemm_tf32(const float* __restrict__ A,
                                                    const float* __restrict__ Bm,
                                                    const float* __restrict__ bias,
                                                    float* __restrict__ Cc,
                                                    int M, int N, int K)
{
    __shared__ unsigned As[3 * GSTRIDE];
    __shared__ unsigned Bs[3 * GSTRIDE];

    const int tid = threadIdx.x;
    const int lane = tid & 31;
    const int wid = tid >> 5;
    const int g = lane >> 2;
    const int c4 = lane & 3;
    const int m0 = blockIdx.y * 128;
    const int n0 = blockIdx.x * 128;
    const int wm = (wid >> 1) * 32;
    const int wn = (wid & 1) * 64;

    const int lrow0 = tid >> 2;           // 0..63, 4 threads/row
    const int lrow1 = lrow0 + 64;
    const int lj = (tid & 3) * 4;         // 0,4,8,12 -> full 16-float k-row

    float acc[2][8][4];
#pragma unroll
    for (int mt = 0; mt < 2; ++mt)
#pragma unroll
        for (int nt = 0; nt < 8; ++nt)
#pragma unroll
            for (int r = 0; r < 4; ++r) acc[mt][nt][r] = 0.f;

    // prologue: issue tiles 0 and 1
#pragma unroll
    for (int p = 0; p < 2; ++p) {
        const int kn = p * 16;
        unsigned* Asn = As + p * GSTRIDE;
        unsigned* Bsn = Bs + p * GSTRIDE;
        cp16(sptr(&Asn[lrow0 * 20 + lj]), A + (long)(m0 + lrow0) * K + kn + lj);
        cp16(sptr(&Asn[lrow1 * 20 + lj]), A + (long)(m0 + lrow1) * K + kn + lj);
        cp16(sptr(&Bsn[lrow0 * 20 + lj]), Bm + (long)(n0 + lrow0) * K + kn + lj);
        cp16(sptr(&Bsn[lrow1 * 20 + lj]), Bm + (long)(n0 + lrow1) * K + kn + lj);
        cp_commit();
    }

    const int NK = K >> 4;
    int cur = 0, nxt = 2;                 // buffer indices mod 3
    for (int i = 0; i < NK; ++i) {
        cp_wait1();                        // tile i arrived (≤1 group in flight)
        __syncthreads();
        if (i + 2 < NK) {
            const int kn = (i + 2) * 16;
            unsigned* Asn = As + nxt * GSTRIDE;
            unsigned* Bsn = Bs + nxt * GSTRIDE;
            cp16(sptr(&Asn[lrow0 * 20 + lj]), A + (long)(m0 + lrow0) * K + kn + lj);
            cp16(sptr(&Asn[lrow1 * 20 + lj]), A + (long)(m0 + lrow1) * K + kn + lj);
            cp16(sptr(&Bsn[lrow0 * 20 + lj]), Bm + (long)(n0 + lrow0) * K + kn + lj);
            cp16(sptr(&Bsn[lrow1 * 20 + lj]), Bm + (long)(n0 + lrow1) * K + kn + lj);
            cp_commit();
        } else {
            cp_commit();                   // keep group count in step
        }

        const unsigned* Asb = As + cur * GSTRIDE;
        const unsigned* Bsb = Bs + cur * GSTRIDE;
#pragma unroll
        for (int ks = 0; ks < 2; ++ks) {
            const int kc = 8 * ks + c4;
            unsigned af[2][4], bf[8][2];
#pragma unroll
            for (int mt = 0; mt < 2; ++mt) {
                int r = wm + 16 * mt + g;
                af[mt][0] = Asb[r * 20 + kc];
                af[mt][1] = Asb[(r + 8) * 20 + kc];
                af[mt][2] = Asb[r * 20 + kc + 4];
                af[mt][3] = Asb[(r + 8) * 20 + kc + 4];
            }
#pragma unroll
            for (int nt = 0; nt < 8; ++nt) {
                int n = wn + 8 * nt + g;
                bf[nt][0] = Bsb[n * 20 + kc];
                bf[nt][1] = Bsb[n * 20 + kc + 4];
            }
#pragma unroll
            for (int mt = 0; mt < 2; ++mt)
#pragma unroll
                for (int nt = 0; nt < 8; ++nt)
                    mma_tf32(acc[mt][nt], af[mt], bf[nt][0], bf[nt][1]);
        }
        cur = (cur == 2) ? 0 : cur + 1;
        nxt = (nxt == 2) ? 0 : nxt + 1;
    }

#pragma unroll
    for (int mt = 0; mt < 2; ++mt) {
#pragma unroll
        for (int nt = 0; nt < 8; ++nt) {
            const int rr = m0 + wm + 16 * mt + g;
            const int cc = n0 + wn + 8 * nt + 2 * c4;
            float b0v = 0.f, b1v = 0.f;
            if (BIAS) { b0v = bias[cc]; b1v = bias[cc + 1]; }
            float2 v0; v0.x = acc[mt][nt][0] + b0v; v0.y = acc[mt][nt][1] + b1v;
            float2 v1; v1.x = acc[mt][nt][2] + b0v; v1.y = acc[mt][nt][3] + b1v;
            *(float2*)(Cc + (long)rr * N + cc) = v0;
            *(float2*)(Cc + (long)(rr + 8) * N + cc) = v1;
        }
    }
}

// ---------------- RoPE + per-head prep (writes tf32-rounded q/k/v) ------------
__global__ void __launch_bounds__(512) rope_kernel(const float* __restrict__ curvp)
{
    const int bt = blockIdx.x;
    const int b = bt / T_;
    const int t = bt % T_;
    const int tid = threadIdx.x;
    const int h = tid >> 5;
    const int j = tid & 31;

    __shared__ float s_inv[32];
    if (tid < 32) s_inv[tid] = (float)pow(10000.0, -(double)tid / 32.0);
    __syncthreads();

    const float* qp = g_qkv + (long)bt * (3 * C_);

    float q1 = qp[h * 64 + j];
    float q2 = qp[h * 64 + 32 + j];
    float k1 = qp[C_ + h * 64 + j];
    float k2 = qp[C_ + h * 64 + 32 + j];

    float fr = (float)t * s_inv[j];
    float cs, sn;
    sincosf(fr, &sn, &cs);

    float q1r = q1 * cs + q2 * sn;
    float q2r = -q1 * sn + q2 * cs;
    float k1r = k1 * cs + k2 * sn;
    float k2r = -k1 * sn + k2 * cs;

    float sq = q1 * q1 + q2 * q2;
    float sk = k1 * k1 + k2 * k2;
#pragma unroll
    for (int o = 16; o > 0; o >>= 1) {
        sq += __shfl_xor_sync(0xffffffffu, sq, o);
        sk += __shfl_xor_sync(0xffffffffu, sk, o);
    }

    float qscale = 1.f, kscale = 1.f;
    if (h < N1_) {
        qscale = 0.125f;
    } else if (h < N1_ + N2_) {
        float curv = curvp[h - N1_];
        if (j == 0) {
            g_tq[(b * N2_ + (h - N1_)) * T_ + t] = sqrtf(1.0f / curv + sq);
            g_tk[(b * N2_ + (h - N1_)) * T_ + t] = sqrtf(1.0f / curv + sk);
        }
    } else {
        qscale = 8.0f / fmaxf(sqrtf(sq), 1e-12f);
        kscale = 1.0f / fmaxf(sqrtf(sk), 1e-12f);
    }

    const long o = ((long)(b * H_ + h) * T_ + t) * HD_;
    g_q[o + j]      = __uint_as_float(f2tf32(q1r * qscale));
    g_q[o + 32 + j] = __uint_as_float(f2tf32(q2r * qscale));
    g_k[o + j]      = __uint_as_float(f2tf32(k1r * kscale));
    g_k[o + 32 + j] = __uint_as_float(f2tf32(k2r * kscale));

    float2 vv = *(const float2*)(qp + 2 * C_ + 2 * tid);
    vv.x = __uint_as_float(f2tf32(vv.x));
    vv.y = __uint_as_float(f2tf32(vv.y));
    *(float2*)(g_v + o + (j * 2)) = vv;
}

// ---------------- attention: FA2-style, tf32 mma, cp.async double-buffer ------
__device__ __forceinline__ float hypscore(float p, float tq, float tk,
                                          float curv, float invsqc) {
    float a = fmaxf(curv * (tq * tk - p), 1.0f + 1e-7f);
    return 1.0f / (1e-6f + invsqc * acoshf(a));
}

__global__ void __launch_bounds__(256) attn_mma(const float* __restrict__ curvp)
{
    __shared__ unsigned Ks[2][64 * 68];   // stride 68 (≡4 mod 32)
    __shared__ unsigned Vs[2][64 * 72];   // stride 72 (≡8 mod 32)
    __shared__ float tks[2][64];

    const int i0 = blockIdx.x * 128;
    const int h  = blockIdx.y;
    const int b  = blockIdx.z;
    const int tid = threadIdx.x;
    const int w = tid >> 5;
    const int lane = tid & 31;
    const int g = lane >> 2;
    const int c4 = lane & 3;
    const int variant = (h < N1_) ? 0 : ((h < N1_ + N2_) ? 1 : 2);
    const long base = (long)(b * H_ + h) * T_ * HD_;
    const int r0 = 16 * w + g;

    // ---- stage Q (two 64-row phases through Ks[0]), build A-fragments --------
    unsigned qa[8][4];
#pragma unroll
    for (int ph = 0; ph < 2; ++ph) {
        for (int idx = tid; idx < 64 * 16; idx += 256) {
            int row = idx >> 4, j = (idx & 15) * 4;
            *(uint4*)&Ks[0][row * 68 + j] =
                *(const uint4*)(g_q + base + (long)(i0 + ph * 64 + row) * HD_ + j);
        }
        __syncthreads();
        if ((w >> 2) == ph) {
            const int rl = 16 * (w & 3) + g;
#pragma unroll
            for (int kt = 0; kt < 8; ++kt) {
                int col = 8 * kt + c4;
                qa[kt][0] = Ks[0][rl * 68 + col];
                qa[kt][1] = Ks[0][(rl + 8) * 68 + col];
                qa[kt][2] = Ks[0][rl * 68 + col + 4];
                qa[kt][3] = Ks[0][(rl + 8) * 68 + col + 4];
            }
        }
        __syncthreads();
    }

    float curv = 0.f, invsqc = 0.f, tq0 = 0.f, tq1 = 0.f;
    const float* tkbase = nullptr;
    if (variant == 1) {
        curv = curvp[h - N1_];
        invsqc = sqrtf(1.0f / curv);
        tq0 = g_tq[(b * N2_ + (h - N1_)) * T_ + i0 + r0];
        tq1 = g_tq[(b * N2_ + (h - N1_)) * T_ + i0 + r0 + 8];
        tkbase = g_tk + (b * N2_ + (h - N1_)) * T_;
    }

    float m0r = -1e30f, m1r = -1e30f, l0 = 0.f, l1 = 0.f;
    float acc[8][4];
#pragma unroll
    for (int nt = 0; nt < 8; ++nt)
#pragma unroll
        for (int r = 0; r < 4; ++r) acc[nt][r] = 0.f;

    const int srcA = (lane & 28) | (c4 >> 1);
    const int srcB = srcA + 2;
    const bool odd = (c4 & 1);
    const int s_last = i0 + ((w >> 2) ? 64 : 0);
    const int s_end = i0 + 64;

    const int crow = tid >> 2;            // 0..63 (copy row; 4 threads/row)
    const int cj = (tid & 3) * 4;         // 0,4,8,12

    // prologue: tile s0=0 into buffer 0 (full 64-float rows: 4 cp16 per thread)
    {
        const float* kg = g_k + base + (long)crow * HD_;
        const float* vg = g_v + base + (long)crow * HD_;
#pragma unroll
        for (int c = 0; c < 4; ++c) {
            cp16(sptr(&Ks[0][crow * 68 + cj + 16 * c]), kg + cj + 16 * c);
            cp16(sptr(&Vs[0][crow * 72 + cj + 16 * c]), vg + cj + 16 * c);
        }
        if (variant == 1 && tid < 16)
            cp16(sptr(&tks[0][tid * 4]), tkbase + tid * 4);
        cp_commit();
    }

    int buf = 0;
    for (int s0 = 0; s0 <= s_end; s0 += 64) {
        cp_wait0();
        __syncthreads();
        if (s0 + 64 <= s_end) {
            const float* kg = g_k + base + (long)(s0 + 64 + crow) * HD_;
            const float* vg = g_v + base + (long)(s0 + 64 + crow) * HD_;
#pragma unroll
            for (int c = 0; c < 4; ++c) {
                cp16(sptr(&Ks[buf ^ 1][crow * 68 + cj + 16 * c]), kg + cj + 16 * c);
                cp16(sptr(&Vs[buf ^ 1][crow * 72 + cj + 16 * c]), vg + cj + 16 * c);
            }
            if (variant == 1 && tid < 16)
                cp16(sptr(&tks[buf ^ 1][tid * 4]), tkbase + s0 + 64 + tid * 4);
            cp_commit();
        }

        if (s0 <= s_last) {
            const unsigned* Kb = Ks[buf];
            const unsigned* Vb = Vs[buf];
            const float* tkb = tks[buf];

            // ---- QK^T ----
            float sc[8][4];
#pragma unroll
            for (int nt = 0; nt < 8; ++nt)
#pragma unroll
                for (int r = 0; r < 4; ++r) sc[nt][r] = 0.f;

#pragma unroll
            for (int nt = 0; nt < 8; ++nt) {
#pragma unroll
                for (int kt = 0; kt < 8; ++kt) {
                    unsigned b0 = Kb[(8 * nt + g) * 68 + 8 * kt + c4];
                    unsigned b1 = Kb[(8 * nt + g) * 68 + 8 * kt + c4 + 4];
                    mma_tf32(sc[nt], qa[kt], b0, b1);
                }
            }

            // ---- transform + mask + row max ----
            const bool domask = (s0 + 63 > i0 + 16 * w);
            const int gr0 = i0 + r0;
            float mloc0 = -1e30f, mloc1 = -1e30f;
#pragma unroll
            for (int nt = 0; nt < 8; ++nt) {
                const int gc = s0 + 8 * nt + 2 * c4;
                if (variant == 1) {
                    float tk0 = tkb[8 * nt + 2 * c4], tk1 = tkb[8 * nt + 2 * c4 + 1];
                    sc[nt][0] = hypscore(sc[nt][0], tq0, tk0, curv, invsqc);
                    sc[nt][1] = hypscore(sc[nt][1], tq0, tk1, curv, invsqc);
                    sc[nt][2] = hypscore(sc[nt][2], tq1, tk0, curv, invsqc);
                    sc[nt][3] = hypscore(sc[nt][3], tq1, tk1, curv, invsqc);
                }
                if (domask) {
                    if (gc > gr0)         sc[nt][0] = -1e30f;
                    if (gc + 1 > gr0)     sc[nt][1] = -1e30f;
                    if (gc > gr0 + 8)     sc[nt][2] = -1e30f;
                    if (gc + 1 > gr0 + 8) sc[nt][3] = -1e30f;
                }
                mloc0 = fmaxf(mloc0, fmaxf(sc[nt][0], sc[nt][1]));
                mloc1 = fmaxf(mloc1, fmaxf(sc[nt][2], sc[nt][3]));
            }
            mloc0 = fmaxf(mloc0, __shfl_xor_sync(0xffffffffu, mloc0, 1));
            mloc0 = fmaxf(mloc0, __shfl_xor_sync(0xffffffffu, mloc0, 2));
            mloc1 = fmaxf(mloc1, __shfl_xor_sync(0xffffffffu, mloc1, 1));
            mloc1 = fmaxf(mloc1, __shfl_xor_sync(0xffffffffu, mloc1, 2));

            const float mn0 = fmaxf(m0r, mloc0);
            const float mn1 = fmaxf(m1r, mloc1);
            const float f0 = __expf(m0r - mn0);
            const float f1 = __expf(m1r - mn1);
            l0 *= f0; l1 *= f1;
#pragma unroll
            for (int nt = 0; nt < 8; ++nt) {
                acc[nt][0] *= f0; acc[nt][1] *= f0;
                acc[nt][2] *= f1; acc[nt][3] *= f1;
            }

            float s0sum = 0.f, s1sum = 0.f;
#pragma unroll
            for (int nt = 0; nt < 8; ++nt) {
                sc[nt][0] = __expf(sc[nt][0] - mn0);
                sc[nt][1] = __expf(sc[nt][1] - mn0);
                sc[nt][2] = __expf(sc[nt][2] - mn1);
                sc[nt][3] = __expf(sc[nt][3] - mn1);
                s0sum += sc[nt][0] + sc[nt][1];
                s1sum += sc[nt][2] + sc[nt][3];
            }
            s0sum += __shfl_xor_sync(0xffffffffu, s0sum, 1);
            s0sum += __shfl_xor_sync(0xffffffffu, s0sum, 2);
            s1sum += __shfl_xor_sync(0xffffffffu, s1sum, 1);
            s1sum += __shfl_xor_sync(0xffffffffu, s1sum, 2);
            l0 += s0sum; l1 += s1sum;
            m0r = mn0; m1r = mn1;

            // ---- P·V ----
#pragma unroll
            for (int kt = 0; kt < 8; ++kt) {
                float x0 = __shfl_sync(0xffffffffu, sc[kt][0], srcA);
                float x1 = __shfl_sync(0xffffffffu, sc[kt][1], srcA);
                float y0 = __shfl_sync(0xffffffffu, sc[kt][0], srcB);
                float y1 = __shfl_sync(0xffffffffu, sc[kt][1], srcB);
                float z0 = __shfl_sync(0xffffffffu, sc[kt][2], srcA);
                float z1 = __shfl_sync(0xffffffffu, sc[kt][3], srcA);
                float u0 = __shfl_sync(0xffffffffu, sc[kt][2], srcB);
                float u1 = __shfl_sync(0xffffffffu, sc[kt][3], srcB);
                unsigned pa[4];
                pa[0] = f2tf32(odd ? x1 : x0);
                pa[1] = f2tf32(odd ? z1 : z0);
                pa[2] = f2tf32(odd ? y1 : y0);
                pa[3] = f2tf32(odd ? u1 : u0);
#pragma unroll
                for (int nt = 0; nt < 8; ++nt) {
                    unsigned b0 = Vb[(8 * kt + c4) * 72 + 8 * nt + g];
                    unsigned b1 = Vb[(8 * kt + c4 + 4) * 72 + 8 * nt + g];
                    mma_tf32(acc[nt], pa, b0, b1);
                }
            }
        }
        buf ^= 1;
    }

    // ---- epilogue (write tf32-rounded so proj GEMM can skip conversion) ----
    const float il0 = 1.0f / l0;
    const float il1 = 1.0f / l1;
    const int r = i0 + r0;
    float* y0p = g_y + (long)(b * T_ + r) * C_ + h * HD_;
    float* y1p = g_y + (long)(b * T_ + r + 8) * C_ + h * HD_;
#pragma unroll
    for (int nt = 0; nt < 8; ++nt) {
        float2 o0, o1;
        o0.x = __uint_as_float(f2tf32(acc[nt][0] * il0));
        o0.y = __uint_as_float(f2tf32(acc[nt][1] * il0));
        o1.x = __uint_as_float(f2tf32(acc[nt][2] * il1));
        o1.y = __uint_as_float(f2tf32(acc[nt][3] * il1));
        *(float2*)(y0p + 8 * nt + 2 * c4) = o0;
        *(float2*)(y1p + 8 * nt + 2 * c4) = o1;
    }
}

// ---------------- launch ------------------------------------------------------
extern "C" void kernel_launch(void* const* d_in, const int* in_sizes, int n_in,
                              void* d_out, int out_size)
{
    const float* x       = (const float*)d_in[0];
    const float* qkv_w   = (const float*)d_in[1];
    const float* proj_w  = (const float*)d_in[2];
    const float* proj_b  = (const float*)d_in[3];
    const float* curv    = (const float*)d_in[4];
    float* out = (float*)d_out;

    float *qkv, *y, *xa, *wa, *pw;
    cudaGetSymbolAddress((void**)&qkv, g_qkv);
    cudaGetSymbolAddress((void**)&y,   g_y);
    cudaGetSymbolAddress((void**)&xa,  g_xa);
    cudaGetSymbolAddress((void**)&wa,  g_wa);
    cudaGetSymbolAddress((void**)&pw,  g_pw);

    // 0) tf32 pre-conversion of GEMM inputs
    prep_tf32<<<(B_ * T_ * C_ / 4 + 255) / 256, 256>>>(x, xa, B_ * T_ * C_ / 4);
    prep_tf32<<<(3 * C_ * C_ / 4 + 255) / 256, 256>>>(qkv_w, wa, 3 * C_ * C_ / 4);
    prep_tf32<<<(C_ * C_ / 4 + 255) / 256, 256>>>(proj_w, pw, C_ * C_ / 4);

    // 1) qkv = x @ qkv_w.T   [4096, 3072]
    gemm_tf32<false><<<dim3((3 * C_) / 128, (B_ * T_) / 128), 256>>>(
        xa, wa, nullptr, qkv, B_ * T_, 3 * C_, C_);

    // 2) rope + head layout + scale folding + hyperbolic tq/tk
    rope_kernel<<<B_ * T_, 512>>>(curv);

    // 3) multi-geometry causal attention (tf32 tensor cores) -> g_y [B,T,C]
    attn_mma<<<dim3(T_ / 128, H_, B_), 256>>>(curv);

    // 4) out = y @ proj_w.T + proj_b
    gemm_tf32<true><<<dim3(C_ / 128, (B_ * T_) / 128), 256>>>(
        y, pw, proj_b, out, B_ * T_, C_, C_);
}

// round 15
// speedup vs baseline: 1.2018x; 1.0252x over previous
#include <cuda_runtime.h>
#include <stdint.h>
#include <math.h>

#define B_  2
#define T_  2048
#define C_  1024
#define H_  16
#define HD_ 64
#define N1_ 6
#define N2_ 4

// ---------------- scratch (device globals; no allocs allowed) ----------------
__device__ float g_qkv[B_ * T_ * 3 * C_];          // [B,T,3C] fp32
__device__ float g_q[B_ * H_ * T_ * HD_];          // [B,H,T,64] tf32-rounded
__device__ float g_k[B_ * H_ * T_ * HD_];          // tf32-rounded
__device__ float g_v[B_ * H_ * T_ * HD_];          // tf32-rounded
__device__ float g_y[B_ * T_ * C_];                // attn out, tf32-rounded
__device__ float g_tq[B_ * N2_ * T_];
__device__ float g_tk[B_ * N2_ * T_];
__device__ float g_xa[B_ * T_ * C_];               // x, tf32-rounded
__device__ float g_wa[3 * C_ * C_];                // qkv_w, tf32-rounded
__device__ float g_pw[C_ * C_];                    // proj_w, tf32-rounded

// ---------------- helpers -----------------------------------------------------
__device__ __forceinline__ unsigned f2tf32(float x) {
    unsigned u;
    asm("cvt.rna.tf32.f32 %0, %1;" : "=r"(u) : "f"(x));
    return u;
}
__device__ __forceinline__ unsigned sptr(const void* p) {
    return (unsigned)__cvta_generic_to_shared(p);
}
__device__ __forceinline__ void cp16(unsigned s, const void* g) {
    asm volatile("cp.async.cg.shared.global [%0], [%1], 16;" :: "r"(s), "l"(g));
}
__device__ __forceinline__ void cp_commit() {
    asm volatile("cp.async.commit_group;");
}
__device__ __forceinline__ void cp_wait0() {
    asm volatile("cp.async.wait_group 0;");
}
__device__ __forceinline__ void cp_wait1() {
    asm volatile("cp.async.wait_group 1;");
}

// D = A(16x8, row) * B(8x8, col) + D, fp32 accum
__device__ __forceinline__ void mma_tf32(float* c, const unsigned* a,
                                         unsigned b0, unsigned b1) {
    asm volatile(
        "mma.sync.aligned.m16n8k8.row.col.f32.tf32.tf32.f32 "
        "{%0,%1,%2,%3}, {%4,%5,%6,%7}, {%8,%9}, {%0,%1,%2,%3};"
        : "+f"(c[0]), "+f"(c[1]), "+f"(c[2]), "+f"(c[3])
        : "r"(a[0]), "r"(a[1]), "r"(a[2]), "r"(a[3]), "r"(b0), "r"(b1));
}

// ---------------- tf32 pre-convert -------------------------------------------
__global__ void prep_tf32(const float* __restrict__ in, float* __restrict__ out,
                          int n4)
{
    int i = blockIdx.x * blockDim.x + threadIdx.x;
    if (i < n4) {
        float4 v = ((const float4*)in)[i];
        uint4 u;
        u.x = f2tf32(v.x); u.y = f2tf32(v.y); u.z = f2tf32(v.z); u.w = f2tf32(v.w);
        ((uint4*)out)[i] = u;
    }
}

// ---------------- GEMM: C[m,n] = sum_k A[m,k]*B[n,k] (+bias[n]) --------------
// Inputs already tf32-rounded. CTA 256 thr, tile 128(M)x64(N), k-chunk 16,
// 3-stage cp.async pipeline. Warp tile 32x32 (8 warps = 4M x 2N).
// Small warp state -> 3 CTAs/SM for latency hiding.
#define ASTRIDE 2560   // 128 rows * 20
#define BSTRIDE 1280   // 64 rows * 20

template <bool BIAS>
__global__ void __launch_bounds__(256, 3) gemm_tf32(const float* __restrict__ A,
                                                    const float* __restrict__ Bm,
                                                    const float* __restrict__ bias,
                                                    float* __restrict__ Cc,
                                                    int M, int N, int K)
{
    __shared__ unsigned As[3 * ASTRIDE];
    __shared__ unsigned Bs[3 * BSTRIDE];

    const int tid = threadIdx.x;
    const int lane = tid & 31;
    const int wid = tid >> 5;
    const int g = lane >> 2;
    const int c4 = lane & 3;
    const int m0 = blockIdx.y * 128;
    const int n0 = blockIdx.x * 64;
    const int wm = (wid >> 1) * 32;       // 0,32,64,96
    const int wn = (wid & 1) * 32;        // 0,32

    const int lrow0 = tid >> 2;           // 0..63
    const int lrow1 = lrow0 + 64;
    const int lj = (tid & 3) * 4;

    float acc[2][4][4];
#pragma unroll
    for (int mt = 0; mt < 2; ++mt)
#pragma unroll
        for (int nt = 0; nt < 4; ++nt)
#pragma unroll
            for (int r = 0; r < 4; ++r) acc[mt][nt][r] = 0.f;

    // prologue: issue tiles 0 and 1
#pragma unroll
    for (int p = 0; p < 2; ++p) {
        const int kn = p * 16;
        unsigned* Asn = As + p * ASTRIDE;
        unsigned* Bsn = Bs + p * BSTRIDE;
        cp16(sptr(&Asn[lrow0 * 20 + lj]), A + (long)(m0 + lrow0) * K + kn + lj);
        cp16(sptr(&Asn[lrow1 * 20 + lj]), A + (long)(m0 + lrow1) * K + kn + lj);
        cp16(sptr(&Bsn[lrow0 * 20 + lj]), Bm + (long)(n0 + lrow0) * K + kn + lj);
        cp_commit();
    }

    const int NK = K >> 4;
    int cur = 0, nxt = 2;                 // buffer indices mod 3
    for (int i = 0; i < NK; ++i) {
        cp_wait1();                        // tile i arrived
        __syncthreads();
        if (i + 2 < NK) {
            const int kn = (i + 2) * 16;
            unsigned* Asn = As + nxt * ASTRIDE;
            unsigned* Bsn = Bs + nxt * BSTRIDE;
            cp16(sptr(&Asn[lrow0 * 20 + lj]), A + (long)(m0 + lrow0) * K + kn + lj);
            cp16(sptr(&Asn[lrow1 * 20 + lj]), A + (long)(m0 + lrow1) * K + kn + lj);
            cp16(sptr(&Bsn[lrow0 * 20 + lj]), Bm + (long)(n0 + lrow0) * K + kn + lj);
            cp_commit();
        } else {
            cp_commit();                   // keep group count in step
        }

        const unsigned* Asb = As + cur * ASTRIDE;
        const unsigned* Bsb = Bs + cur * BSTRIDE;
#pragma unroll
        for (int ks = 0; ks < 2; ++ks) {
            const int kc = 8 * ks + c4;
            unsigned af[2][4], bf[4][2];
#pragma unroll
            for (int mt = 0; mt < 2; ++mt) {
                int r = wm + 16 * mt + g;
                af[mt][0] = Asb[r * 20 + kc];
                af[mt][1] = Asb[(r + 8) * 20 + kc];
                af[mt][2] = Asb[r * 20 + kc + 4];
                af[mt][3] = Asb[(r + 8) * 20 + kc + 4];
            }
#pragma unroll
            for (int nt = 0; nt < 4; ++nt) {
                int n = wn + 8 * nt + g;
                bf[nt][0] = Bsb[n * 20 + kc];
                bf[nt][1] = Bsb[n * 20 + kc + 4];
            }
#pragma unroll
            for (int mt = 0; mt < 2; ++mt)
#pragma unroll
                for (int nt = 0; nt < 4; ++nt)
                    mma_tf32(acc[mt][nt], af[mt], bf[nt][0], bf[nt][1]);
        }
        cur = (cur == 2) ? 0 : cur + 1;
        nxt = (nxt == 2) ? 0 : nxt + 1;
    }

#pragma unroll
    for (int mt = 0; mt < 2; ++mt) {
#pragma unroll
        for (int nt = 0; nt < 4; ++nt) {
            const int rr = m0 + wm + 16 * mt + g;
            const int cc = n0 + wn + 8 * nt + 2 * c4;
            float b0v = 0.f, b1v = 0.f;
            if (BIAS) { b0v = bias[cc]; b1v = bias[cc + 1]; }
            float2 v0; v0.x = acc[mt][nt][0] + b0v; v0.y = acc[mt][nt][1] + b1v;
            float2 v1; v1.x = acc[mt][nt][2] + b0v; v1.y = acc[mt][nt][3] + b1v;
            *(float2*)(Cc + (long)rr * N + cc) = v0;
            *(float2*)(Cc + (long)(rr + 8) * N + cc) = v1;
        }
    }
}

// ---------------- RoPE + per-head prep (writes tf32-rounded q/k/v) ------------
__global__ void __launch_bounds__(512) rope_kernel(const float* __restrict__ curvp)
{
    const int bt = blockIdx.x;
    const int b = bt / T_;
    const int t = bt % T_;
    const int tid = threadIdx.x;
    const int h = tid >> 5;
    const int j = tid & 31;

    __shared__ float s_inv[32];
    if (tid < 32) s_inv[tid] = (float)pow(10000.0, -(double)tid / 32.0);
    __syncthreads();

    const float* qp = g_qkv + (long)bt * (3 * C_);

    float q1 = qp[h * 64 + j];
    float q2 = qp[h * 64 + 32 + j];
    float k1 = qp[C_ + h * 64 + j];
    float k2 = qp[C_ + h * 64 + 32 + j];

    float fr = (float)t * s_inv[j];
    float cs, sn;
    sincosf(fr, &sn, &cs);

    float q1r = q1 * cs + q2 * sn;
    float q2r = -q1 * sn + q2 * cs;
    float k1r = k1 * cs + k2 * sn;
    float k2r = -k1 * sn + k2 * cs;

    float sq = q1 * q1 + q2 * q2;
    float sk = k1 * k1 + k2 * k2;
#pragma unroll
    for (int o = 16; o > 0; o >>= 1) {
        sq += __shfl_xor_sync(0xffffffffu, sq, o);
        sk += __shfl_xor_sync(0xffffffffu, sk, o);
    }

    float qscale = 1.f, kscale = 1.f;
    if (h < N1_) {
        qscale = 0.125f;
    } else if (h < N1_ + N2_) {
        float curv = curvp[h - N1_];
        if (j == 0) {
            g_tq[(b * N2_ + (h - N1_)) * T_ + t] = sqrtf(1.0f / curv + sq);
            g_tk[(b * N2_ + (h - N1_)) * T_ + t] = sqrtf(1.0f / curv + sk);
        }
    } else {
        qscale = 8.0f / fmaxf(sqrtf(sq), 1e-12f);
        kscale = 1.0f / fmaxf(sqrtf(sk), 1e-12f);
    }

    const long o = ((long)(b * H_ + h) * T_ + t) * HD_;
    g_q[o + j]      = __uint_as_float(f2tf32(q1r * qscale));
    g_q[o + 32 + j] = __uint_as_float(f2tf32(q2r * qscale));
    g_k[o + j]      = __uint_as_float(f2tf32(k1r * kscale));
    g_k[o + 32 + j] = __uint_as_float(f2tf32(k2r * kscale));

    float2 vv = *(const float2*)(qp + 2 * C_ + 2 * tid);
    vv.x = __uint_as_float(f2tf32(vv.x));
    vv.y = __uint_as_float(f2tf32(vv.y));
    *(float2*)(g_v + o + (j * 2)) = vv;
}

// ---------------- attention: FA2-style, tf32 mma, cp.async double-buffer ------
// fast acosh: valid for a >= 1 (here a ~ 50-70, far from the cancellation zone)
__device__ __forceinline__ float hypscore(float p, float tq, float tk,
                                          float curv, float invsqc) {
    float a = fmaxf(curv * (tq * tk - p), 1.0f + 1e-7f);
    float t = a + sqrtf(fmaf(a, a, -1.0f));
    return 1.0f / (1e-6f + invsqc * __logf(t));
}

__global__ void __launch_bounds__(256) attn_mma(const float* __restrict__ curvp)
{
    __shared__ unsigned Ks[2][64 * 68];   // stride 68 (≡4 mod 32)
    __shared__ unsigned Vs[2][64 * 72];   // stride 72 (≡8 mod 32)
    __shared__ float tks[2][64];

    // heavy-first: launch order is x-major, so map the LAST bids to the
    // LIGHTEST q-tiles -> short completion tail.
    const int i0 = (gridDim.x - 1 - blockIdx.x) * 128;
    const int h  = blockIdx.y;
    const int b  = blockIdx.z;
    const int tid = threadIdx.x;
    const int w = tid >> 5;
    const int lane = tid & 31;
    const int g = lane >> 2;
    const int c4 = lane & 3;
    const int variant = (h < N1_) ? 0 : ((h < N1_ + N2_) ? 1 : 2);
    const long base = (long)(b * H_ + h) * T_ * HD_;
    const int r0 = 16 * w + g;

    // ---- stage Q (two 64-row phases through Ks[0]), build A-fragments --------
    unsigned qa[8][4];
#pragma unroll
    for (int ph = 0; ph < 2; ++ph) {
        for (int idx = tid; idx < 64 * 16; idx += 256) {
            int row = idx >> 4, j = (idx & 15) * 4;
            *(uint4*)&Ks[0][row * 68 + j] =
                *(const uint4*)(g_q + base + (long)(i0 + ph * 64 + row) * HD_ + j);
        }
        __syncthreads();
        if ((w >> 2) == ph) {
            const int rl = 16 * (w & 3) + g;
#pragma unroll
            for (int kt = 0; kt < 8; ++kt) {
                int col = 8 * kt + c4;
                qa[kt][0] = Ks[0][rl * 68 + col];
                qa[kt][1] = Ks[0][(rl + 8) * 68 + col];
                qa[kt][2] = Ks[0][rl * 68 + col + 4];
                qa[kt][3] = Ks[0][(rl + 8) * 68 + col + 4];
            }
        }
        __syncthreads();
    }

    float curv = 0.f, invsqc = 0.f, tq0 = 0.f, tq1 = 0.f;
    const float* tkbase = nullptr;
    if (variant == 1) {
        curv = curvp[h - N1_];
        invsqc = sqrtf(1.0f / curv);
        tq0 = g_tq[(b * N2_ + (h - N1_)) * T_ + i0 + r0];
        tq1 = g_tq[(b * N2_ + (h - N1_)) * T_ + i0 + r0 + 8];
        tkbase = g_tk + (b * N2_ + (h - N1_)) * T_;
    }

    float m0r = -1e30f, m1r = -1e30f, l0 = 0.f, l1 = 0.f;
    float acc[8][4];
#pragma unroll
    for (int nt = 0; nt < 8; ++nt)
#pragma unroll
        for (int r = 0; r < 4; ++r) acc[nt][r] = 0.f;

    const int srcA = (lane & 28) | (c4 >> 1);
    const int srcB = srcA + 2;
    const bool odd = (c4 & 1);
    const int s_last = i0 + ((w >> 2) ? 64 : 0);
    const int s_end = i0 + 64;

    const int crow = tid >> 2;            // 0..63 (copy row; 4 threads/row)
    const int cj = (tid & 3) * 4;         // 0,4,8,12

    // prologue: tile s0=0 into buffer 0 (full 64-float rows: 4 cp16 per thread)
    {
        const float* kg = g_k + base + (long)crow * HD_;
        const float* vg = g_v + base + (long)crow * HD_;
#pragma unroll
        for (int c = 0; c < 4; ++c) {
            cp16(sptr(&Ks[0][crow * 68 + cj + 16 * c]), kg + cj + 16 * c);
            cp16(sptr(&Vs[0][crow * 72 + cj + 16 * c]), vg + cj + 16 * c);
        }
        if (variant == 1 && tid < 16)
            cp16(sptr(&tks[0][tid * 4]), tkbase + tid * 4);
        cp_commit();
    }

    int buf = 0;
    for (int s0 = 0; s0 <= s_end; s0 += 64) {
        cp_wait0();
        __syncthreads();
        if (s0 + 64 <= s_end) {
            const float* kg = g_k + base + (long)(s0 + 64 + crow) * HD_;
            const float* vg = g_v + base + (long)(s0 + 64 + crow) * HD_;
#pragma unroll
            for (int c = 0; c < 4; ++c) {
                cp16(sptr(&Ks[buf ^ 1][crow * 68 + cj + 16 * c]), kg + cj + 16 * c);
                cp16(sptr(&Vs[buf ^ 1][crow * 72 + cj + 16 * c]), vg + cj + 16 * c);
            }
            if (variant == 1 && tid < 16)
                cp16(sptr(&tks[buf ^ 1][tid * 4]), tkbase + s0 + 64 + tid * 4);
            cp_commit();
        }

        if (s0 <= s_last) {
            const unsigned* Kb = Ks[buf];
            const unsigned* Vb = Vs[buf];
            const float* tkb = tks[buf];

            // ---- QK^T ----
            float sc[8][4];
#pragma unroll
            for (int nt = 0; nt < 8; ++nt)
#pragma unroll
                for (int r = 0; r < 4; ++r) sc[nt][r] = 0.f;

#pragma unroll
            for (int nt = 0; nt < 8; ++nt) {
#pragma unroll
                for (int kt = 0; kt < 8; ++kt) {
                    unsigned b0 = Kb[(8 * nt + g) * 68 + 8 * kt + c4];
                    unsigned b1 = Kb[(8 * nt + g) * 68 + 8 * kt + c4 + 4];
                    mma_tf32(sc[nt], qa[kt], b0, b1);
                }
            }

            // ---- transform + mask + row max ----
            const bool domask = (s0 + 63 > i0 + 16 * w);
            const int gr0 = i0 + r0;
            float mloc0 = -1e30f, mloc1 = -1e30f;
#pragma unroll
            for (int nt = 0; nt < 8; ++nt) {
                const int gc = s0 + 8 * nt + 2 * c4;
                if (variant == 1) {
                    float tk0 = tkb[8 * nt + 2 * c4], tk1 = tkb[8 * nt + 2 * c4 + 1];
                    sc[nt][0] = hypscore(sc[nt][0], tq0, tk0, curv, invsqc);
                    sc[nt][1] = hypscore(sc[nt][1], tq0, tk1, curv, invsqc);
                    sc[nt][2] = hypscore(sc[nt][2], tq1, tk0, curv, invsqc);
                    sc[nt][3] = hypscore(sc[nt][3], tq1, tk1, curv, invsqc);
                }
                if (domask) {
                    if (gc > gr0)         sc[nt][0] = -1e30f;
                    if (gc + 1 > gr0)     sc[nt][1] = -1e30f;
                    if (gc > gr0 + 8)     sc[nt][2] = -1e30f;
                    if (gc + 1 > gr0 + 8) sc[nt][3] = -1e30f;
                }
                mloc0 = fmaxf(mloc0, fmaxf(sc[nt][0], sc[nt][1]));
                mloc1 = fmaxf(mloc1, fmaxf(sc[nt][2], sc[nt][3]));
            }
            mloc0 = fmaxf(mloc0, __shfl_xor_sync(0xffffffffu, mloc0, 1));
            mloc0 = fmaxf(mloc0, __shfl_xor_sync(0xffffffffu, mloc0, 2));
            mloc1 = fmaxf(mloc1, __shfl_xor_sync(0xffffffffu, mloc1, 1));
            mloc1 = fmaxf(mloc1, __shfl_xor_sync(0xffffffffu, mloc1, 2));

            const float mn0 = fmaxf(m0r, mloc0);
            const float mn1 = fmaxf(m1r, mloc1);
            const float f0 = __expf(m0r - mn0);
            const float f1 = __expf(m1r - mn1);
            l0 *= f0; l1 *= f1;
#pragma unroll
            for (int nt = 0; nt < 8; ++nt) {
                acc[nt][0] *= f0; acc[nt][1] *= f0;
                acc[nt][2] *= f1; acc[nt][3] *= f1;
            }

            float s0sum = 0.f, s1sum = 0.f;
#pragma unroll
            for (int nt = 0; nt < 8; ++nt) {
                sc[nt][0] = __expf(sc[nt][0] - mn0);
                sc[nt][1] = __expf(sc[nt][1] - mn0);
                sc[nt][2] = __expf(sc[nt][2] - mn1);
                sc[nt][3] = __expf(sc[nt][3] - mn1);
                s0sum += sc[nt][0] + sc[nt][1];
                s1sum += sc[nt][2] + sc[nt][3];
            }
            s0sum += __shfl_xor_sync(0xffffffffu, s0sum, 1);
            s0sum += __shfl_xor_sync(0xffffffffu, s0sum, 2);
            s1sum += __shfl_xor_sync(0xffffffffu, s1sum, 1);
            s1sum += __shfl_xor_sync(0xffffffffu, s1sum, 2);
            l0 += s0sum; l1 += s1sum;
            m0r = mn0; m1r = mn1;

            // ---- P·V ----
#pragma unroll
            for (int kt = 0; kt < 8; ++kt) {
                float x0 = __shfl_sync(0xffffffffu, sc[kt][0], srcA);
                float x1 = __shfl_sync(0xffffffffu, sc[kt][1], srcA);
                float y0 = __shfl_sync(0xffffffffu, sc[kt][0], srcB);
                float y1 = __shfl_sync(0xffffffffu, sc[kt][1], srcB);
                float z0 = __shfl_sync(0xffffffffu, sc[kt][2], srcA);
                float z1 = __shfl_sync(0xffffffffu, sc[kt][3], srcA);
                float u0 = __shfl_sync(0xffffffffu, sc[kt][2], srcB);
                float u1 = __shfl_sync(0xffffffffu, sc[kt][3], srcB);
                unsigned pa[4];
                pa[0] = f2tf32(odd ? x1 : x0);
                pa[1] = f2tf32(odd ? z1 : z0);
                pa[2] = f2tf32(odd ? y1 : y0);
                pa[3] = f2tf32(odd ? u1 : u0);
#pragma unroll
                for (int nt = 0; nt < 8; ++nt) {
                    unsigned b0 = Vb[(8 * kt + c4) * 72 + 8 * nt + g];
                    unsigned b1 = Vb[(8 * kt + c4 + 4) * 72 + 8 * nt + g];
                    mma_tf32(acc[nt], pa, b0, b1);
                }
            }
        }
        buf ^= 1;
    }

    // ---- epilogue (write tf32-rounded so proj GEMM can skip conversion) ----
    const float il0 = 1.0f / l0;
    const float il1 = 1.0f / l1;
    const int r = i0 + r0;
    float* y0p = g_y + (long)(b * T_ + r) * C_ + h * HD_;
    float* y1p = g_y + (long)(b * T_ + r + 8) * C_ + h * HD_;
#pragma unroll
    for (int nt = 0; nt < 8; ++nt) {
        float2 o0, o1;
        o0.x = __uint_as_float(f2tf32(acc[nt][0] * il0));
        o0.y = __uint_as_float(f2tf32(acc[nt][1] * il0));
        o1.x = __uint_as_float(f2tf32(acc[nt][2] * il1));
        o1.y = __uint_as_float(f2tf32(acc[nt][3] * il1));
        *(float2*)(y0p + 8 * nt + 2 * c4) = o0;
        *(float2*)(y1p + 8 * nt + 2 * c4) = o1;
    }
}

// ---------------- launch ------------------------------------------------------
extern "C" void kernel_launch(void* const* d_in, const int* in_sizes, int n_in,
                              void* d_out, int out_size)
{
    const float* x       = (const float*)d_in[0];
    const float* qkv_w   = (const float*)d_in[1];
    const float* proj_w  = (const float*)d_in[2];
    const float* proj_b  = (const float*)d_in[3];
    const float* curv    = (const float*)d_in[4];
    float* out = (float*)d_out;

    float *qkv, *y, *xa, *wa, *pw;
    cudaGetSymbolAddress((void**)&qkv, g_qkv);
    cudaGetSymbolAddress((void**)&y,   g_y);
    cudaGetSymbolAddress((void**)&xa,  g_xa);
    cudaGetSymbolAddress((void**)&wa,  g_wa);
    cudaGetSymbolAddress((void**)&pw,  g_pw);

    // 0) tf32 pre-conversion of GEMM inputs
    prep_tf32<<<(B_ * T_ * C_ / 4 + 255) / 256, 256>>>(x, xa, B_ * T_ * C_ / 4);
    prep_tf32<<<(3 * C_ * C_ / 4 + 255) / 256, 256>>>(qkv_w, wa, 3 * C_ * C_ / 4);
    prep_tf32<<<(C_ * C_ / 4 + 255) / 256, 256>>>(proj_w, pw, C_ * C_ / 4);

    // 1) qkv = x @ qkv_w.T   [4096, 3072]
    gemm_tf32<false><<<dim3((3 * C_) / 64, (B_ * T_) / 128), 256>>>(
        xa, wa, nullptr, qkv, B_ * T_, 3 * C_, C_);

    // 2) rope + head layout + scale folding + hyperbolic tq/tk
    rope_kernel<<<B_ * T_, 512>>>(curv);

    // 3) multi-geometry causal attention (tf32 tensor cores) -> g_y [B,T,C]
    attn_mma<<<dim3(T_ / 128, H_, B_), 256>>>(curv);

    // 4) out = y @ proj_w.T + proj_b
    gemm_tf32<true><<<dim3(C_ / 64, (B_ * T_) / 128), 256>>>(
        y, pw, proj_b, out, B_ * T_, C_, C_);
}

// round 17
// speedup vs baseline: 1.3440x; 1.1183x over previous
#include <cuda_runtime.h>
#include <stdint.h>
#include <math.h>

#define B_  2
#define T_  2048
#define C_  1024
#define H_  16
#define HD_ 64
#define N1_ 6
#define N2_ 4

// ---------------- scratch (device globals; no allocs allowed) ----------------
__device__ float g_qkv[B_ * T_ * 3 * C_];          // [B,T,3C] fp32
__device__ float g_q[B_ * H_ * T_ * HD_];          // [B,H,T,64] tf32-rounded
__device__ float g_k[B_ * H_ * T_ * HD_];          // tf32-rounded
__device__ float g_v[B_ * H_ * T_ * HD_];          // tf32-rounded
__device__ float g_y[B_ * T_ * C_];                // attn out, tf32, PAIR-PERMUTED k-layout
__device__ float g_tq[B_ * N2_ * T_];
__device__ float g_tk[B_ * N2_ * T_];
__device__ float g_xa[B_ * T_ * C_];               // x, tf32, pair-permuted
__device__ float g_wa[3 * C_ * C_];                // qkv_w, tf32, pair-permuted
__device__ float g_pw[C_ * C_];                    // proj_w, tf32, pair-permuted

// ---------------- helpers -----------------------------------------------------
__device__ __forceinline__ unsigned f2tf32(float x) {
    unsigned u;
    asm("cvt.rna.tf32.f32 %0, %1;" : "=r"(u) : "f"(x));
    return u;
}
__device__ __forceinline__ unsigned sptr(const void* p) {
    return (unsigned)__cvta_generic_to_shared(p);
}
__device__ __forceinline__ void cp16(unsigned s, const void* g) {
    asm volatile("cp.async.cg.shared.global [%0], [%1], 16;" :: "r"(s), "l"(g));
}
__device__ __forceinline__ void cp_commit() {
    asm volatile("cp.async.commit_group;");
}
__device__ __forceinline__ void cp_wait0() {
    asm volatile("cp.async.wait_group 0;");
}
__device__ __forceinline__ void cp_wait1() {
    asm volatile("cp.async.wait_group 1;");
}

// D = A(16x8, row) * B(8x8, col) + D, fp32 accum
__device__ __forceinline__ void mma_tf32(float* c, const unsigned* a,
                                         unsigned b0, unsigned b1) {
    asm volatile(
        "mma.sync.aligned.m16n8k8.row.col.f32.tf32.tf32.f32 "
        "{%0,%1,%2,%3}, {%4,%5,%6,%7}, {%8,%9}, {%0,%1,%2,%3};"
        : "+f"(c[0]), "+f"(c[1]), "+f"(c[2]), "+f"(c[3])
        : "r"(a[0]), "r"(a[1]), "r"(a[2]), "r"(a[3]), "r"(b0), "r"(b1));
}

// ---------------- tf32 pre-convert WITH pair permutation ----------------------
// Within each 8-element k-group, store order (0,4),(1,5),(2,6),(3,7).
// Thread handles one 8-group (2 float4 in, 2 uint4 out).
__global__ void prep_tf32_perm(const float* __restrict__ in,
                               float* __restrict__ out, int n8)
{
    int i = blockIdx.x * blockDim.x + threadIdx.x;
    if (i < n8) {
        const float4* in4 = (const float4*)in;
        float4 a = in4[2 * i];
        float4 b = in4[2 * i + 1];
        uint4 q0, q1;
        q0.x = f2tf32(a.x); q0.y = f2tf32(b.x);   // o0, o4
        q0.z = f2tf32(a.y); q0.w = f2tf32(b.y);   // o1, o5
        q1.x = f2tf32(a.z); q1.y = f2tf32(b.z);   // o2, o6
        q1.z = f2tf32(a.w); q1.w = f2tf32(b.w);   // o3, o7
        ((uint4*)out)[2 * i] = q0;
        ((uint4*)out)[2 * i + 1] = q1;
    }
}

// ---------------- GEMM: C[m,n] = sum_k A[m,k]*B[n,k] (+bias[n]) --------------
// A, B tf32 pair-permuted. CTA 256 thr, tile 128x128, k-chunk 16, 3-stage
// cp.async pipeline. Warp tile 32x64. Fragments via LDS.64 (uint2).
// Row stride 24 (S%32==8 -> conflict-free uint2 per half-warp; 96B rows 16B-aligned).
#define GSTR 3072   // 128 rows * 24

template <bool BIAS>
__global__ void __launch_bounds__(256, 2) gemm_tf32(const float* __restrict__ A,
                                                    const float* __restrict__ Bm,
                                                    const float* __restrict__ bias,
                                                    float* __restrict__ Cc,
                                                    int M, int N, int K)
{
    __shared__ unsigned As[3 * GSTR];
    __shared__ unsigned Bs[3 * GSTR];

    const int tid = threadIdx.x;
    const int lane = tid & 31;
    const int wid = tid >> 5;
    const int g = lane >> 2;
    const int c4 = lane & 3;
    const int m0 = blockIdx.y * 128;
    const int n0 = blockIdx.x * 128;
    const int wm = (wid >> 1) * 32;
    const int wn = (wid & 1) * 64;

    const int lrow0 = tid >> 2;           // 0..63
    const int lrow1 = lrow0 + 64;
    const int lj = (tid & 3) * 4;

    float acc[2][8][4];
#pragma unroll
    for (int mt = 0; mt < 2; ++mt)
#pragma unroll
        for (int nt = 0; nt < 8; ++nt)
#pragma unroll
            for (int r = 0; r < 4; ++r) acc[mt][nt][r] = 0.f;

    // prologue: issue tiles 0 and 1
#pragma unroll
    for (int p = 0; p < 2; ++p) {
        const int kn = p * 16;
        unsigned* Asn = As + p * GSTR;
        unsigned* Bsn = Bs + p * GSTR;
        cp16(sptr(&Asn[lrow0 * 24 + lj]), A + (long)(m0 + lrow0) * K + kn + lj);
        cp16(sptr(&Asn[lrow1 * 24 + lj]), A + (long)(m0 + lrow1) * K + kn + lj);
        cp16(sptr(&Bsn[lrow0 * 24 + lj]), Bm + (long)(n0 + lrow0) * K + kn + lj);
        cp16(sptr(&Bsn[lrow1 * 24 + lj]), Bm + (long)(n0 + lrow1) * K + kn + lj);
        cp_commit();
    }

    const int NK = K >> 4;
    int cur = 0, nxt = 2;
    for (int i = 0; i < NK; ++i) {
        cp_wait1();
        __syncthreads();
        if (i + 2 < NK) {
            const int kn = (i + 2) * 16;
            unsigned* Asn = As + nxt * GSTR;
            unsigned* Bsn = Bs + nxt * GSTR;
            cp16(sptr(&Asn[lrow0 * 24 + lj]), A + (long)(m0 + lrow0) * K + kn + lj);
            cp16(sptr(&Asn[lrow1 * 24 + lj]), A + (long)(m0 + lrow1) * K + kn + lj);
            cp16(sptr(&Bsn[lrow0 * 24 + lj]), Bm + (long)(n0 + lrow0) * K + kn + lj);
            cp16(sptr(&Bsn[lrow1 * 24 + lj]), Bm + (long)(n0 + lrow1) * K + kn + lj);
            cp_commit();
        } else {
            cp_commit();
        }

        const unsigned* Asb = As + cur * GSTR;
        const unsigned* Bsb = Bs + cur * GSTR;
#pragma unroll
        for (int ks = 0; ks < 2; ++ks) {
            const int kc2 = 8 * ks + 2 * c4;    // stored pair position
            unsigned af[2][4], bf[8][2];
#pragma unroll
            for (int mt = 0; mt < 2; ++mt) {
                int r = wm + 16 * mt + g;
                uint2 lo = *(const uint2*)&Asb[r * 24 + kc2];
                uint2 hi = *(const uint2*)&Asb[(r + 8) * 24 + kc2];
                af[mt][0] = lo.x; af[mt][1] = hi.x;
                af[mt][2] = lo.y; af[mt][3] = hi.y;
            }
#pragma unroll
            for (int nt = 0; nt < 8; ++nt) {
                int n = wn + 8 * nt + g;
                uint2 bb = *(const uint2*)&Bsb[n * 24 + kc2];
                bf[nt][0] = bb.x; bf[nt][1] = bb.y;
            }
#pragma unroll
            for (int mt = 0; mt < 2; ++mt)
#pragma unroll
                for (int nt = 0; nt < 8; ++nt)
                    mma_tf32(acc[mt][nt], af[mt], bf[nt][0], bf[nt][1]);
        }
        cur = (cur == 2) ? 0 : cur + 1;
        nxt = (nxt == 2) ? 0 : nxt + 1;
    }

#pragma unroll
    for (int mt = 0; mt < 2; ++mt) {
#pragma unroll
        for (int nt = 0; nt < 8; ++nt) {
            const int rr = m0 + wm + 16 * mt + g;
            const int cc = n0 + wn + 8 * nt + 2 * c4;
            float b0v = 0.f, b1v = 0.f;
            if (BIAS) { b0v = bias[cc]; b1v = bias[cc + 1]; }
            float2 v0; v0.x = acc[mt][nt][0] + b0v; v0.y = acc[mt][nt][1] + b1v;
            float2 v1; v1.x = acc[mt][nt][2] + b0v; v1.y = acc[mt][nt][3] + b1v;
            *(float2*)(Cc + (long)rr * N + cc) = v0;
            *(float2*)(Cc + (long)(rr + 8) * N + cc) = v1;
        }
    }
}

// ---------------- RoPE + per-head prep (writes tf32-rounded q/k/v) ------------
__global__ void __launch_bounds__(512) rope_kernel(const float* __restrict__ curvp)
{
    const int bt = blockIdx.x;
    const int b = bt / T_;
    const int t = bt % T_;
    const int tid = threadIdx.x;
    const int h = tid >> 5;
    const int j = tid & 31;

    __shared__ float s_inv[32];
    if (tid < 32) s_inv[tid] = (float)pow(10000.0, -(double)tid / 32.0);
    __syncthreads();

    const float* qp = g_qkv + (long)bt * (3 * C_);

    float q1 = qp[h * 64 + j];
    float q2 = qp[h * 64 + 32 + j];
    float k1 = qp[C_ + h * 64 + j];
    float k2 = qp[C_ + h * 64 + 32 + j];

    float fr = (float)t * s_inv[j];
    float cs, sn;
    sincosf(fr, &sn, &cs);

    float q1r = q1 * cs + q2 * sn;
    float q2r = -q1 * sn + q2 * cs;
    float k1r = k1 * cs + k2 * sn;
    float k2r = -k1 * sn + k2 * cs;

    float sq = q1 * q1 + q2 * q2;
    float sk = k1 * k1 + k2 * k2;
#pragma unroll
    for (int o = 16; o > 0; o >>= 1) {
        sq += __shfl_xor_sync(0xffffffffu, sq, o);
        sk += __shfl_xor_sync(0xffffffffu, sk, o);
    }

    float qscale = 1.f, kscale = 1.f;
    if (h < N1_) {
        qscale = 0.125f;
    } else if (h < N1_ + N2_) {
        float curv = curvp[h - N1_];
        if (j == 0) {
            g_tq[(b * N2_ + (h - N1_)) * T_ + t] = sqrtf(1.0f / curv + sq);
            g_tk[(b * N2_ + (h - N1_)) * T_ + t] = sqrtf(1.0f / curv + sk);
        }
    } else {
        qscale = 8.0f / fmaxf(sqrtf(sq), 1e-12f);
        kscale = 1.0f / fmaxf(sqrtf(sk), 1e-12f);
    }

    const long o = ((long)(b * H_ + h) * T_ + t) * HD_;
    g_q[o + j]      = __uint_as_float(f2tf32(q1r * qscale));
    g_q[o + 32 + j] = __uint_as_float(f2tf32(q2r * qscale));
    g_k[o + j]      = __uint_as_float(f2tf32(k1r * kscale));
    g_k[o + 32 + j] = __uint_as_float(f2tf32(k2r * kscale));

    float2 vv = *(const float2*)(qp + 2 * C_ + 2 * tid);
    vv.x = __uint_as_float(f2tf32(vv.x));
    vv.y = __uint_as_float(f2tf32(vv.y));
    *(float2*)(g_v + o + (j * 2)) = vv;
}

// ---------------- attention: FA2-style, tf32 mma, cp.async double-buffer ------
__device__ __forceinline__ float hypscore(float p, float tq, float tk,
                                          float curv, float invsqc) {
    float a = fmaxf(curv * (tq * tk - p), 1.0f + 1e-7f);
    float t = a + sqrtf(fmaf(a, a, -1.0f));
    return 1.0f / (1e-6f + invsqc * __logf(t));
}

__global__ void __launch_bounds__(256) attn_mma(const float* __restrict__ curvp)
{
    __shared__ unsigned Ks[2][64 * 68];   // stride 68 (≡4 mod 32)
    __shared__ unsigned Vs[2][64 * 72];   // stride 72 (≡8 mod 32)
    __shared__ float tks[2][64];

    // heavy-first scheduling
    const int i0 = (gridDim.x - 1 - blockIdx.x) * 128;
    const int h  = blockIdx.y;
    const int b  = blockIdx.z;
    const int tid = threadIdx.x;
    const int w = tid >> 5;
    const int lane = tid & 31;
    const int g = lane >> 2;
    const int c4 = lane & 3;
    const int variant = (h < N1_) ? 0 : ((h < N1_ + N2_) ? 1 : 2);
    const long base = (long)(b * H_ + h) * T_ * HD_;
    const int r0 = 16 * w + g;

    // ---- stage Q (two 64-row phases through Ks[0]), build A-fragments --------
    unsigned qa[8][4];
#pragma unroll
    for (int ph = 0; ph < 2; ++ph) {
        for (int idx = tid; idx < 64 * 16; idx += 256) {
            int row = idx >> 4, j = (idx & 15) * 4;
            *(uint4*)&Ks[0][row * 68 + j] =
                *(const uint4*)(g_q + base + (long)(i0 + ph * 64 + row) * HD_ + j);
        }
        __syncthreads();
        if ((w >> 2) == ph) {
            const int rl = 16 * (w & 3) + g;
#pragma unroll
            for (int kt = 0; kt < 8; ++kt) {
                int col = 8 * kt + c4;
                qa[kt][0] = Ks[0][rl * 68 + col];
                qa[kt][1] = Ks[0][(rl + 8) * 68 + col];
                qa[kt][2] = Ks[0][rl * 68 + col + 4];
                qa[kt][3] = Ks[0][(rl + 8) * 68 + col + 4];
            }
        }
        __syncthreads();
    }

    float curv = 0.f, invsqc = 0.f, tq0 = 0.f, tq1 = 0.f;
    const float* tkbase = nullptr;
    if (variant == 1) {
        curv = curvp[h - N1_];
        invsqc = sqrtf(1.0f / curv);
        tq0 = g_tq[(b * N2_ + (h - N1_)) * T_ + i0 + r0];
        tq1 = g_tq[(b * N2_ + (h - N1_)) * T_ + i0 + r0 + 8];
        tkbase = g_tk + (b * N2_ + (h - N1_)) * T_;
    }

    float m0r = -1e30f, m1r = -1e30f, l0 = 0.f, l1 = 0.f;
    float acc[8][4];
#pragma unroll
    for (int nt = 0; nt < 8; ++nt)
#pragma unroll
        for (int r = 0; r < 4; ++r) acc[nt][r] = 0.f;

    const int srcA = (lane & 28) | (c4 >> 1);
    const int srcB = srcA + 2;
    const bool odd = (c4 & 1);
    const int s_last = i0 + ((w >> 2) ? 64 : 0);
    const int s_end = i0 + 64;

    const int crow = tid >> 2;
    const int cj = (tid & 3) * 4;

    // prologue: tile s0=0 into buffer 0
    {
        const float* kg = g_k + base + (long)crow * HD_;
        const float* vg = g_v + base + (long)crow * HD_;
#pragma unroll
        for (int c = 0; c < 4; ++c) {
            cp16(sptr(&Ks[0][crow * 68 + cj + 16 * c]), kg + cj + 16 * c);
            cp16(sptr(&Vs[0][crow * 72 + cj + 16 * c]), vg + cj + 16 * c);
        }
        if (variant == 1 && tid < 16)
            cp16(sptr(&tks[0][tid * 4]), tkbase + tid * 4);
        cp_commit();
    }

    int buf = 0;
    for (int s0 = 0; s0 <= s_end; s0 += 64) {
        cp_wait0();
        __syncthreads();
        if (s0 + 64 <= s_end) {
            const float* kg = g_k + base + (long)(s0 + 64 + crow) * HD_;
            const float* vg = g_v + base + (long)(s0 + 64 + crow) * HD_;
#pragma unroll
            for (int c = 0; c < 4; ++c) {
                cp16(sptr(&Ks[buf ^ 1][crow * 68 + cj + 16 * c]), kg + cj + 16 * c);
                cp16(sptr(&Vs[buf ^ 1][crow * 72 + cj + 16 * c]), vg + cj + 16 * c);
            }
            if (variant == 1 && tid < 16)
                cp16(sptr(&tks[buf ^ 1][tid * 4]), tkbase + s0 + 64 + tid * 4);
            cp_commit();
        }

        if (s0 <= s_last) {
            const unsigned* Kb = Ks[buf];
            const unsigned* Vb = Vs[buf];
            const float* tkb = tks[buf];

            // ---- QK^T (kt outer: consecutive mmas independent) ----
            float sc[8][4];
#pragma unroll
            for (int nt = 0; nt < 8; ++nt)
#pragma unroll
                for (int r = 0; r < 4; ++r) sc[nt][r] = 0.f;

#pragma unroll
            for (int kt = 0; kt < 8; ++kt) {
#pragma unroll
                for (int nt = 0; nt < 8; ++nt) {
                    unsigned b0 = Kb[(8 * nt + g) * 68 + 8 * kt + c4];
                    unsigned b1 = Kb[(8 * nt + g) * 68 + 8 * kt + c4 + 4];
                    mma_tf32(sc[nt], qa[kt], b0, b1);
                }
            }

            // ---- transform + mask + row max ----
            const bool domask = (s0 + 63 > i0 + 16 * w);
            const int gr0 = i0 + r0;
            float mloc0 = -1e30f, mloc1 = -1e30f;
#pragma unroll
            for (int nt = 0; nt < 8; ++nt) {
                const int gc = s0 + 8 * nt + 2 * c4;
                if (variant == 1) {
                    float tk0 = tkb[8 * nt + 2 * c4], tk1 = tkb[8 * nt + 2 * c4 + 1];
                    sc[nt][0] = hypscore(sc[nt][0], tq0, tk0, curv, invsqc);
                    sc[nt][1] = hypscore(sc[nt][1], tq0, tk1, curv, invsqc);
                    sc[nt][2] = hypscore(sc[nt][2], tq1, tk0, curv, invsqc);
                    sc[nt][3] = hypscore(sc[nt][3], tq1, tk1, curv, invsqc);
                }
                if (domask) {
                    if (gc > gr0)         sc[nt][0] = -1e30f;
                    if (gc + 1 > gr0)     sc[nt][1] = -1e30f;
                    if (gc > gr0 + 8)     sc[nt][2] = -1e30f;
                    if (gc + 1 > gr0 + 8) sc[nt][3] = -1e30f;
                }
                mloc0 = fmaxf(mloc0, fmaxf(sc[nt][0], sc[nt][1]));
                mloc1 = fmaxf(mloc1, fmaxf(sc[nt][2], sc[nt][3]));
            }
            mloc0 = fmaxf(mloc0, __shfl_xor_sync(0xffffffffu, mloc0, 1));
            mloc0 = fmaxf(mloc0, __shfl_xor_sync(0xffffffffu, mloc0, 2));
            mloc1 = fmaxf(mloc1, __shfl_xor_sync(0xffffffffu, mloc1, 1));
            mloc1 = fmaxf(mloc1, __shfl_xor_sync(0xffffffffu, mloc1, 2));

            const float mn0 = fmaxf(m0r, mloc0);
            const float mn1 = fmaxf(m1r, mloc1);
            const float f0 = __expf(m0r - mn0);
            const float f1 = __expf(m1r - mn1);
            l0 *= f0; l1 *= f1;
#pragma unroll
            for (int nt = 0; nt < 8; ++nt) {
                acc[nt][0] *= f0; acc[nt][1] *= f0;
                acc[nt][2] *= f1; acc[nt][3] *= f1;
            }

            float s0sum = 0.f, s1sum = 0.f;
#pragma unroll
            for (int nt = 0; nt < 8; ++nt) {
                sc[nt][0] = __expf(sc[nt][0] - mn0);
                sc[nt][1] = __expf(sc[nt][1] - mn0);
                sc[nt][2] = __expf(sc[nt][2] - mn1);
                sc[nt][3] = __expf(sc[nt][3] - mn1);
                s0sum += sc[nt][0] + sc[nt][1];
                s1sum += sc[nt][2] + sc[nt][3];
            }
            s0sum += __shfl_xor_sync(0xffffffffu, s0sum, 1);
            s0sum += __shfl_xor_sync(0xffffffffu, s0sum, 2);
            s1sum += __shfl_xor_sync(0xffffffffu, s1sum, 1);
            s1sum += __shfl_xor_sync(0xffffffffu, s1sum, 2);
            l0 += s0sum; l1 += s1sum;
            m0r = mn0; m1r = mn1;

            // ---- P·V ----
#pragma unroll
            for (int kt = 0; kt < 8; ++kt) {
                float x0 = __shfl_sync(0xffffffffu, sc[kt][0], srcA);
                float x1 = __shfl_sync(0xffffffffu, sc[kt][1], srcA);
                float y0 = __shfl_sync(0xffffffffu, sc[kt][0], srcB);
                float y1 = __shfl_sync(0xffffffffu, sc[kt][1], srcB);
                float z0 = __shfl_sync(0xffffffffu, sc[kt][2], srcA);
                float z1 = __shfl_sync(0xffffffffu, sc[kt][3], srcA);
                float u0 = __shfl_sync(0xffffffffu, sc[kt][2], srcB);
                float u1 = __shfl_sync(0xffffffffu, sc[kt][3], srcB);
                unsigned pa[4];
                pa[0] = f2tf32(odd ? x1 : x0);
                pa[1] = f2tf32(odd ? z1 : z0);
                pa[2] = f2tf32(odd ? y1 : y0);
                pa[3] = f2tf32(odd ? u1 : u0);
#pragma unroll
                for (int nt = 0; nt < 8; ++nt) {
                    unsigned b0 = Vb[(8 * kt + c4) * 72 + 8 * nt + g];
                    unsigned b1 = Vb[(8 * kt + c4 + 4) * 72 + 8 * nt + g];
                    mma_tf32(acc[nt], pa, b0, b1);
                }
            }
        }
        buf ^= 1;
    }

    // ---- epilogue: tf32-rounded, PAIR-PERMUTED within each 8-col group so
    //      proj GEMM can consume g_y directly with uint2 fragment loads.
    //      orig col c=2*c4 -> pos p0 = (c<4 ? 2c : 2(c-4)+1) = {0,4,1,5}[c4];
    //      orig col c+1 -> pos p0+2.
    const float il0 = 1.0f / l0;
    const float il1 = 1.0f / l1;
    const int r = i0 + r0;
    const int p0 = (c4 < 2) ? (4 * c4) : (4 * c4 - 7);
    float* y0p = g_y + (long)(b * T_ + r) * C_ + h * HD_;
    float* y1p = g_y + (long)(b * T_ + r + 8) * C_ + h * HD_;
#pragma unroll
    for (int nt = 0; nt < 8; ++nt) {
        y0p[8 * nt + p0]     = __uint_as_float(f2tf32(acc[nt][0] * il0));
        y0p[8 * nt + p0 + 2] = __uint_as_float(f2tf32(acc[nt][1] * il0));
        y1p[8 * nt + p0]     = __uint_as_float(f2tf32(acc[nt][2] * il1));
        y1p[8 * nt + p0 + 2] = __uint_as_float(f2tf32(acc[nt][3] * il1));
    }
}

// ---------------- launch ------------------------------------------------------
extern "C" void kernel_launch(void* const* d_in, const int* in_sizes, int n_in,
                              void* d_out, int out_size)
{
    const float* x       = (const float*)d_in[0];
    const float* qkv_w   = (const float*)d_in[1];
    const float* proj_w  = (const float*)d_in[2];
    const float* proj_b  = (const float*)d_in[3];
    const float* curv    = (const float*)d_in[4];
    float* out = (float*)d_out;

    float *qkv, *y, *xa, *wa, *pw;
    cudaGetSymbolAddress((void**)&qkv, g_qkv);
    cudaGetSymbolAddress((void**)&y,   g_y);
    cudaGetSymbolAddress((void**)&xa,  g_xa);
    cudaGetSymbolAddress((void**)&wa,  g_wa);
    cudaGetSymbolAddress((void**)&pw,  g_pw);

    // 0) tf32 pre-conversion + pair-permutation of GEMM operands
    prep_tf32_perm<<<(B_ * T_ * C_ / 8 + 255) / 256, 256>>>(x, xa, B_ * T_ * C_ / 8);
    prep_tf32_perm<<<(3 * C_ * C_ / 8 + 255) / 256, 256>>>(qkv_w, wa, 3 * C_ * C_ / 8);
    prep_tf32_perm<<<(C_ * C_ / 8 + 255) / 256, 256>>>(proj_w, pw, C_ * C_ / 8);

    // 1) qkv = x @ qkv_w.T   [4096, 3072]
    gemm_tf32<false><<<dim3((3 * C_) / 128, (B_ * T_) / 128), 256>>>(
        xa, wa, nullptr, qkv, B_ * T_, 3 * C_, C_);

    // 2) rope + head layout + scale folding + hyperbolic tq/tk
    rope_kernel<<<B_ * T_, 512>>>(curv);

    // 3) multi-geometry causal attention (tf32 tensor cores) -> g_y (permuted)
    attn_mma<<<dim3(T_ / 128, H_, B_), 256>>>(curv);

    // 4) out = y @ proj_w.T + proj_b
    gemm_tf32<true><<<dim3(C_ / 128, (B_ * T_) / 128), 256>>>(
        y, pw, proj_b, out, B_ * T_, C_, C_);
}